// round 1
// baseline (speedup 1.0000x reference)
#include <cuda_runtime.h>
#include <cuda_bf16.h>
#include <math.h>

// ---------------------------------------------------------------------------
// Problem constants
// ---------------------------------------------------------------------------
#define LQ      8160
#define DMODEL  256
#define NHEADS  8
#define DHEAD   32
#define NLEV    4
// per-level grids: W = 48>>l, H = (T*H) = 128>>l
__constant__ int c_lstart[4] = {0, 6144, 7680, 8064};

// ---------------------------------------------------------------------------
// Scratch (device globals; no allocation allowed)
// ---------------------------------------------------------------------------
__device__ float g_value [LQ * DMODEL];   // input_flatten @ Wv + bv
__device__ float g_coff  [LQ * 256];      // query @ Ws + bs
__device__ float g_catt  [LQ * 128];      // query @ Wa + ba
__device__ float g_tsoff [LQ * 256];      // query @ Wts + bts
__device__ float g_tatt  [LQ * 128];      // query @ Wta + bta
__device__ float g_outh  [LQ * DMODEL];   // per-head sampled output

// ---------------------------------------------------------------------------
// SGEMM: C[M,N] = A[M,K] @ B[K,N] + bias[N]   (all row-major fp32)
// BM=128 BN=128 BK=8, 256 threads, 8x8 per-thread microtile.
// N must be a multiple of 128; K a multiple of 8; M guarded.
// ---------------------------------------------------------------------------
#define BM 128
#define BN 128
#define BK 8
#define TM 8
#define TN 8

__global__ __launch_bounds__(256) void sgemm_bias(
    const float* __restrict__ A, const float* __restrict__ B,
    const float* __restrict__ bias, float* __restrict__ C,
    int M, int N, int K)
{
    __shared__ float As[BK][BM];
    __shared__ float Bs[BK][BN];

    const int bx = blockIdx.x;           // N tile
    const int by = blockIdx.y;           // M tile
    const int tid = threadIdx.x;

    const int trow = tid / (BN / TN);    // 0..15
    const int tcol = tid % (BN / TN);    // 0..15

    // A tile load mapping: 128 rows x 8 cols, one float4 per thread
    const int aRow = tid >> 1;           // 0..127
    const int aCol = (tid & 1) * 4;      // 0 or 4
    // B tile load mapping: 8 rows x 128 cols, one float4 per thread
    const int bRow = tid >> 5;           // 0..7
    const int bCol = (tid & 31) * 4;     // 0..124

    float acc[TM][TN];
    #pragma unroll
    for (int i = 0; i < TM; i++)
        #pragma unroll
        for (int j = 0; j < TN; j++) acc[i][j] = 0.f;

    float ra[TM], rb[TN];

    for (int k0 = 0; k0 < K; k0 += BK) {
        const int gr = by * BM + aRow;
        float4 av = make_float4(0.f, 0.f, 0.f, 0.f);
        if (gr < M) av = *(const float4*)(A + (size_t)gr * K + k0 + aCol);
        As[aCol + 0][aRow] = av.x;
        As[aCol + 1][aRow] = av.y;
        As[aCol + 2][aRow] = av.z;
        As[aCol + 3][aRow] = av.w;

        float4 bvv = *(const float4*)(B + (size_t)(k0 + bRow) * N + bx * BN + bCol);
        *(float4*)&Bs[bRow][bCol] = bvv;

        __syncthreads();

        #pragma unroll
        for (int k = 0; k < BK; k++) {
            #pragma unroll
            for (int i = 0; i < TM; i++) ra[i] = As[k][trow * TM + i];
            #pragma unroll
            for (int j = 0; j < TN; j++) rb[j] = Bs[k][tcol * TN + j];
            #pragma unroll
            for (int i = 0; i < TM; i++)
                #pragma unroll
                for (int j = 0; j < TN; j++)
                    acc[i][j] = fmaf(ra[i], rb[j], acc[i][j]);
        }
        __syncthreads();
    }

    #pragma unroll
    for (int i = 0; i < TM; i++) {
        const int r = by * BM + trow * TM + i;
        if (r >= M) continue;
        #pragma unroll
        for (int j = 0; j < TN; j += 4) {
            const int c = bx * BN + tcol * TN + j;
            float4 v;
            v.x = acc[i][j + 0] + bias[c + 0];
            v.y = acc[i][j + 1] + bias[c + 1];
            v.z = acc[i][j + 2] + bias[c + 2];
            v.w = acc[i][j + 3] + bias[c + 3];
            *(float4*)(C + (size_t)r * N + c) = v;
        }
    }
}

// ---------------------------------------------------------------------------
// Sampling kernel: one warp per (q, head). Lane = channel d (0..31).
// Fuses: location computation, joint softmax over 32 points, bilinear gather,
// weighted accumulation. Writes g_outh[q*256 + head*32 + d].
// ---------------------------------------------------------------------------
__global__ __launch_bounds__(256) void sample_kernel(
    const float* __restrict__ ref,     // (LQ, 4, 2)
    const float* __restrict__ toff,    // (LQ, 4, 2, 2)
    const float* __restrict__ c_off,   // (LQ, 256): head,lev,4,2
    const float* __restrict__ c_att,   // (LQ, 128): head,16
    const float* __restrict__ ts_off,  // (LQ, 256): head,lev,tw,nt,2
    const float* __restrict__ t_att,   // (LQ, 128): head,16
    const float* __restrict__ value,   // (8160, 256): row, head*32+d
    float* __restrict__ outh)          // (LQ, 256)
{
    __shared__ float sw[8][32];
    __shared__ float sx[8][32];
    __shared__ float sy[8][32];

    const int wid   = threadIdx.x >> 5;
    const int lane  = threadIdx.x & 31;
    const int wglob = blockIdx.x * 8 + wid;
    const int q     = wglob >> 3;
    const int head  = wglob & 7;

    // ---- setup: lane == point index p (0..31) ----
    {
        const int p = lane;
        const int l = p >> 3;
        const int j = p & 7;
        const float Wl = (float)(48 >> l);
        const float Hl = (float)(128 >> l);

        const float refx = ref[q * 8 + l * 2 + 0];
        const float refy = ref[q * 8 + l * 2 + 1];

        float lg, lx, ly;
        if (j < 4) {
            lg = c_att[q * 128 + head * 16 + l * 4 + j];
            const float ox = c_off[q * 256 + head * 32 + l * 8 + j * 2 + 0];
            const float oy = c_off[q * 256 + head * 32 + l * 8 + j * 2 + 1];
            lx = refx + ox / Wl;
            ly = refy + oy / Hl;
        } else {
            const int kk = j - 4;
            const int tw = kk >> 1;
            lg = t_att[q * 128 + head * 16 + l * 4 + kk];
            const float ox = ts_off[q * 256 + head * 32 + l * 8 + kk * 2 + 0];
            const float oy = ts_off[q * 256 + head * 32 + l * 8 + kk * 2 + 1];
            const float tx = toff[q * 16 + l * 4 + tw * 2 + 0];
            const float ty = toff[q * 16 + l * 4 + tw * 2 + 1];
            lx = refx + tx + ox / Wl;
            ly = refy + ty + oy / Hl;
        }

        // joint softmax over all 32 points (warp-wide)
        float m = lg;
        #pragma unroll
        for (int o = 16; o > 0; o >>= 1)
            m = fmaxf(m, __shfl_xor_sync(0xffffffffu, m, o));
        float e = expf(lg - m);
        float s = e;
        #pragma unroll
        for (int o = 16; o > 0; o >>= 1)
            s += __shfl_xor_sync(0xffffffffu, s, o);

        sw[wid][p] = e / s;
        sx[wid][p] = lx * Wl - 0.5f;   // pixel-space x
        sy[wid][p] = ly * Hl - 0.5f;   // pixel-space y
    }
    __syncwarp();

    // ---- accumulate: lane == channel d ----
    const int d = lane;
    float acc = 0.f;

    #pragma unroll 8
    for (int p = 0; p < 32; p++) {
        const int l  = p >> 3;
        const int W  = 48 >> l;
        const int H  = 128 >> l;
        const int st = c_lstart[l];

        const float wgt = sw[wid][p];
        const float gx  = sx[wid][p];
        const float gy  = sy[wid][p];

        const float fx0 = floorf(gx), fy0 = floorf(gy);
        const int ix0 = (int)fx0, iy0 = (int)fy0;
        const int ix1 = ix0 + 1,  iy1 = iy0 + 1;
        const float wx = gx - fx0, wy = gy - fy0;

        const bool vx0 = (ix0 >= 0) & (ix0 < W);
        const bool vx1 = (ix1 >= 0) & (ix1 < W);
        const bool vy0 = (iy0 >= 0) & (iy0 < H);
        const bool vy1 = (iy1 >= 0) & (iy1 < H);

        const float* base = value + (size_t)st * 256 + head * 32 + d;

        const float v00 = (vx0 & vy0) ? base[(iy0 * W + ix0) * 256] : 0.f;
        const float v10 = (vx1 & vy0) ? base[(iy0 * W + ix1) * 256] : 0.f;
        const float v01 = (vx0 & vy1) ? base[(iy1 * W + ix0) * 256] : 0.f;
        const float v11 = (vx1 & vy1) ? base[(iy1 * W + ix1) * 256] : 0.f;

        const float bil = v00 * (1.f - wx) * (1.f - wy)
                        + v10 * wx * (1.f - wy)
                        + v01 * (1.f - wx) * wy
                        + v11 * wx * wy;
        acc = fmaf(wgt, bil, acc);
    }

    outh[q * 256 + head * 32 + d] = acc;
}

// ---------------------------------------------------------------------------
// Launch
// ---------------------------------------------------------------------------
static float* sym_addr(const void* sym)
{
    void* p = nullptr;
    cudaGetSymbolAddress(&p, sym);
    return (float*)p;
}

extern "C" void kernel_launch(void* const* d_in, const int* in_sizes, int n_in,
                              void* d_out, int out_size)
{
    const float* query = (const float*)d_in[0];
    const float* ref   = (const float*)d_in[1];
    const float* toff  = (const float*)d_in[2];
    const float* inp   = (const float*)d_in[3];
    // d_in[4] (shapes), d_in[5] (starts) are compile-time constants here
    const float* Wv  = (const float*)d_in[6];
    const float* bv  = (const float*)d_in[7];
    const float* Ws  = (const float*)d_in[8];
    const float* bs  = (const float*)d_in[9];
    const float* Wa  = (const float*)d_in[10];
    const float* ba  = (const float*)d_in[11];
    const float* Wts = (const float*)d_in[12];
    const float* bts = (const float*)d_in[13];
    const float* Wta = (const float*)d_in[14];
    const float* bta = (const float*)d_in[15];
    const float* Wo  = (const float*)d_in[16];
    const float* bo  = (const float*)d_in[17];

    float* value = sym_addr(g_value);
    float* coff  = sym_addr(g_coff);
    float* catt  = sym_addr(g_catt);
    float* tsoff = sym_addr(g_tsoff);
    float* tatt  = sym_addr(g_tatt);
    float* outh  = sym_addr(g_outh);

    const dim3 blk(256);
    const int mby = (LQ + BM - 1) / BM;   // 64

    sgemm_bias<<<dim3(2, mby), blk>>>(inp,   Wv,  bv,  value, LQ, 256, 256);
    sgemm_bias<<<dim3(2, mby), blk>>>(query, Ws,  bs,  coff,  LQ, 256, 256);
    sgemm_bias<<<dim3(1, mby), blk>>>(query, Wa,  ba,  catt,  LQ, 128, 256);
    sgemm_bias<<<dim3(2, mby), blk>>>(query, Wts, bts, tsoff, LQ, 256, 256);
    sgemm_bias<<<dim3(1, mby), blk>>>(query, Wta, bta, tatt,  LQ, 128, 256);

    sample_kernel<<<LQ, 256>>>(ref, toff, coff, catt, tsoff, tatt, value, outh);

    sgemm_bias<<<dim3(2, mby), blk>>>(outh, Wo, bo, (float*)d_out, LQ, 256, 256);
}

// round 3
// speedup vs baseline: 1.3365x; 1.3365x over previous
#include <cuda_runtime.h>
#include <cuda_bf16.h>
#include <math.h>

// ---------------------------------------------------------------------------
// Problem constants
// ---------------------------------------------------------------------------
#define LQ      8160
#define DMODEL  256

__constant__ int c_lstart[4] = {0, 6144, 7680, 8064};

// ---------------------------------------------------------------------------
// Scratch (device globals; no allocation allowed)
// ---------------------------------------------------------------------------
// Fused projection buffer, per row (stride 768):
//   [0,256)   c_off  (query@Ws+bs)
//   [256,384) c_att  (query@Wa+ba)
//   [384,640) ts_off (query@Wts+bts)
//   [640,768) t_att  (query@Wta+bta)
__device__ float g_proj  [LQ * 768];
__device__ float g_value [LQ * DMODEL];
__device__ float g_outh  [LQ * DMODEL];

// ---------------------------------------------------------------------------
// Double-buffered SGEMM tile: C[*,128] = A[M,256] @ B[256,128] + bias
// BN=128, BK=16, 256 threads, TN=8. BM_/TM_ templated.
// A is row-major lda=256 (K). B row-major with given ldb. C row-major ldc.
// B/bias/C pre-offset to the 128-wide column tile.
// ---------------------------------------------------------------------------
template<int BM_, int TM_>
__device__ __forceinline__ void gemm_tile(
    const float* __restrict__ A,
    const float* __restrict__ B, int ldb,
    const float* __restrict__ bias,
    float* __restrict__ C, int ldc,
    int mt)
{
    constexpr int BN_ = 128, BK_ = 16, TN_ = 8;
    constexpr int APASS = BM_ / 64;
    constexpr int KTILES = 256 / BK_;   // 16

    __shared__ float As[2][BK_][BM_];
    __shared__ float Bs[2][BK_][BN_];

    const int tid  = threadIdx.x;
    const int trow = tid >> 4;          // 0..15
    const int tcol = tid & 15;          // 0..15
    const int aRow = tid >> 2;          // 0..63
    const int aCol = (tid & 3) << 2;    // 0,4,8,12
    const int bRow = tid >> 5;          // 0..7
    const int bCol = (tid & 31) << 2;   // 0..124

    float4 aP[APASS], bP[2];

    // prologue: tile 0 -> smem[0]
    #pragma unroll
    for (int p = 0; p < APASS; p++) {
        const int r  = aRow + p * 64;
        const int gr = mt * BM_ + r;
        float4 v = make_float4(0.f, 0.f, 0.f, 0.f);
        if (gr < LQ) v = *(const float4*)(A + (size_t)gr * 256 + aCol);
        As[0][aCol + 0][r] = v.x; As[0][aCol + 1][r] = v.y;
        As[0][aCol + 2][r] = v.z; As[0][aCol + 3][r] = v.w;
    }
    #pragma unroll
    for (int p = 0; p < 2; p++)
        *(float4*)&Bs[0][bRow + p * 8][bCol] =
            *(const float4*)(B + (size_t)(bRow + p * 8) * ldb + bCol);
    __syncthreads();

    float acc[TM_][TN_];
    #pragma unroll
    for (int i = 0; i < TM_; i++)
        #pragma unroll
        for (int j = 0; j < TN_; j++) acc[i][j] = 0.f;

    int buf = 0;
    for (int t = 0; t < KTILES; t++) {
        const int nk = t + 1;
        if (nk < KTILES) {
            const int k0 = nk * BK_;
            #pragma unroll
            for (int p = 0; p < APASS; p++) {
                const int gr = mt * BM_ + aRow + p * 64;
                aP[p] = make_float4(0.f, 0.f, 0.f, 0.f);
                if (gr < LQ) aP[p] = *(const float4*)(A + (size_t)gr * 256 + k0 + aCol);
            }
            #pragma unroll
            for (int p = 0; p < 2; p++)
                bP[p] = *(const float4*)(B + (size_t)(k0 + bRow + p * 8) * ldb + bCol);
        }
        #pragma unroll
        for (int k = 0; k < BK_; k++) {
            float ra[TM_], rb[TN_];
            #pragma unroll
            for (int i = 0; i < TM_; i += 4)
                *(float4*)&ra[i] = *(const float4*)&As[buf][k][trow * TM_ + i];
            *(float4*)&rb[0] = *(const float4*)&Bs[buf][k][tcol * TN_ + 0];
            *(float4*)&rb[4] = *(const float4*)&Bs[buf][k][tcol * TN_ + 4];
            #pragma unroll
            for (int i = 0; i < TM_; i++)
                #pragma unroll
                for (int j = 0; j < TN_; j++)
                    acc[i][j] = fmaf(ra[i], rb[j], acc[i][j]);
        }
        if (nk < KTILES) {
            const int nb = buf ^ 1;
            #pragma unroll
            for (int p = 0; p < APASS; p++) {
                const int r = aRow + p * 64;
                As[nb][aCol + 0][r] = aP[p].x; As[nb][aCol + 1][r] = aP[p].y;
                As[nb][aCol + 2][r] = aP[p].z; As[nb][aCol + 3][r] = aP[p].w;
            }
            #pragma unroll
            for (int p = 0; p < 2; p++)
                *(float4*)&Bs[nb][bRow + p * 8][bCol] = bP[p];
            __syncthreads();
            buf = nb;
        }
    }

    #pragma unroll
    for (int i = 0; i < TM_; i++) {
        const int r = mt * BM_ + trow * TM_ + i;
        if (r >= LQ) continue;
        #pragma unroll
        for (int j = 0; j < TN_; j += 4) {
            const int c = tcol * TN_ + j;
            float4 v;
            v.x = acc[i][j + 0] + bias[c + 0];
            v.y = acc[i][j + 1] + bias[c + 1];
            v.z = acc[i][j + 2] + bias[c + 2];
            v.w = acc[i][j + 3] + bias[c + 3];
            *(float4*)(C + (size_t)r * ldc + c) = v;
        }
    }
}

// ---------------------------------------------------------------------------
// Fused projection GEMM: one launch covers
//   tiles [0,384):   query @ {Ws,Wa,Wts,Wta} -> g_proj (ldc=768)
//   tiles [384,512): input_flatten @ Wv      -> g_value (ldc=256)
// ---------------------------------------------------------------------------
__global__ __launch_bounds__(256, 2) void proj_kernel(
    const float* __restrict__ query, const float* __restrict__ inp,
    const float* __restrict__ Wv,  const float* __restrict__ bv,
    const float* __restrict__ Ws,  const float* __restrict__ bs,
    const float* __restrict__ Wa,  const float* __restrict__ ba,
    const float* __restrict__ Wts, const float* __restrict__ bts,
    const float* __restrict__ Wta, const float* __restrict__ bta,
    float* __restrict__ proj, float* __restrict__ value)
{
    const int t = blockIdx.x;
    const float *A, *B, *bias;
    float* C;
    int ldb, ldc, mt;

    if (t < 384) {
        mt = t / 6;
        const int nt = t % 6;
        A = query; ldc = 768; C = proj + nt * 128;
        switch (nt) {
            case 0:  B = Ws;        bias = bs;        ldb = 256; break;
            case 1:  B = Ws + 128;  bias = bs + 128;  ldb = 256; break;
            case 2:  B = Wa;        bias = ba;        ldb = 128; break;
            case 3:  B = Wts;       bias = bts;       ldb = 256; break;
            case 4:  B = Wts + 128; bias = bts + 128; ldb = 256; break;
            default: B = Wta;       bias = bta;       ldb = 128; break;
        }
    } else {
        const int u = t - 384;
        mt = u >> 1;
        const int nt = u & 1;
        A = inp; B = Wv + nt * 128; bias = bv + nt * 128; ldb = 256;
        C = value + nt * 128; ldc = 256;
    }
    gemm_tile<128, 8>(A, B, ldb, bias, C, ldc, mt);
}

// Output GEMM: BM=64 for better fill (256 blocks)
__global__ __launch_bounds__(256, 2) void out_kernel(
    const float* __restrict__ outh, const float* __restrict__ Wo,
    const float* __restrict__ bo, float* __restrict__ out)
{
    const int mt = blockIdx.x >> 1;
    const int nt = blockIdx.x & 1;
    gemm_tile<64, 4>(outh, Wo + nt * 128, 256, bo + nt * 128,
                     out + nt * 128, 256, mt);
}

// ---------------------------------------------------------------------------
// Sampling kernel: one warp per (q, head). Lane = channel d (0..31).
// ---------------------------------------------------------------------------
__global__ __launch_bounds__(256) void sample_kernel(
    const float* __restrict__ ref,     // (LQ, 4, 2)
    const float* __restrict__ toff,    // (LQ, 4, 2, 2)
    const float* __restrict__ proj,    // (LQ, 768) fused projections
    const float* __restrict__ value,   // (8160, 256)
    float* __restrict__ outh)          // (LQ, 256)
{
    __shared__ float sw[8][32];
    __shared__ float sx[8][32];
    __shared__ float sy[8][32];

    const int wid   = threadIdx.x >> 5;
    const int lane  = threadIdx.x & 31;
    const int wglob = blockIdx.x * 8 + wid;
    const int q     = wglob >> 3;
    const int head  = wglob & 7;

    const float* prow = proj + (size_t)q * 768;

    // ---- setup: lane == point index p (0..31) ----
    {
        const int p = lane;
        const int l = p >> 3;
        const int j = p & 7;
        const float Wl = (float)(48 >> l);
        const float Hl = (float)(128 >> l);

        const float refx = ref[q * 8 + l * 2 + 0];
        const float refy = ref[q * 8 + l * 2 + 1];

        float lg, lx, ly;
        if (j < 4) {
            lg = prow[256 + head * 16 + l * 4 + j];
            const float ox = prow[head * 32 + l * 8 + j * 2 + 0];
            const float oy = prow[head * 32 + l * 8 + j * 2 + 1];
            lx = refx + ox / Wl;
            ly = refy + oy / Hl;
        } else {
            const int kk = j - 4;
            const int tw = kk >> 1;
            lg = prow[640 + head * 16 + l * 4 + kk];
            const float ox = prow[384 + head * 32 + l * 8 + kk * 2 + 0];
            const float oy = prow[384 + head * 32 + l * 8 + kk * 2 + 1];
            const float tx = toff[q * 16 + l * 4 + tw * 2 + 0];
            const float ty = toff[q * 16 + l * 4 + tw * 2 + 1];
            lx = refx + tx + ox / Wl;
            ly = refy + ty + oy / Hl;
        }

        // joint softmax over all 32 points (warp-wide)
        float m = lg;
        #pragma unroll
        for (int o = 16; o > 0; o >>= 1)
            m = fmaxf(m, __shfl_xor_sync(0xffffffffu, m, o));
        float e = expf(lg - m);
        float s = e;
        #pragma unroll
        for (int o = 16; o > 0; o >>= 1)
            s += __shfl_xor_sync(0xffffffffu, s, o);

        sw[wid][p] = e / s;
        sx[wid][p] = lx * Wl - 0.5f;
        sy[wid][p] = ly * Hl - 0.5f;
    }
    __syncwarp();

    // ---- accumulate: lane == channel d ----
    const int d = lane;
    float acc = 0.f;

    #pragma unroll 8
    for (int p = 0; p < 32; p++) {
        const int l  = p >> 3;
        const int W  = 48 >> l;
        const int H  = 128 >> l;
        const int st = c_lstart[l];

        const float wgt = sw[wid][p];
        const float gx  = sx[wid][p];
        const float gy  = sy[wid][p];

        const float fx0 = floorf(gx), fy0 = floorf(gy);
        const int ix0 = (int)fx0, iy0 = (int)fy0;
        const int ix1 = ix0 + 1,  iy1 = iy0 + 1;
        const float wx = gx - fx0, wy = gy - fy0;

        const bool vx0 = (ix0 >= 0) & (ix0 < W);
        const bool vx1 = (ix1 >= 0) & (ix1 < W);
        const bool vy0 = (iy0 >= 0) & (iy0 < H);
        const bool vy1 = (iy1 >= 0) & (iy1 < H);

        const float* base = value + (size_t)st * 256 + head * 32 + d;

        const float v00 = (vx0 & vy0) ? base[(iy0 * W + ix0) * 256] : 0.f;
        const float v10 = (vx1 & vy0) ? base[(iy0 * W + ix1) * 256] : 0.f;
        const float v01 = (vx0 & vy1) ? base[(iy1 * W + ix0) * 256] : 0.f;
        const float v11 = (vx1 & vy1) ? base[(iy1 * W + ix1) * 256] : 0.f;

        const float bil = v00 * (1.f - wx) * (1.f - wy)
                        + v10 * wx * (1.f - wy)
                        + v01 * (1.f - wx) * wy
                        + v11 * wx * wy;
        acc = fmaf(wgt, bil, acc);
    }

    outh[q * 256 + head * 32 + d] = acc;
}

// ---------------------------------------------------------------------------
// Launch
// ---------------------------------------------------------------------------
static float* sym_addr(const void* sym)
{
    void* p = nullptr;
    cudaGetSymbolAddress(&p, sym);
    return (float*)p;
}

extern "C" void kernel_launch(void* const* d_in, const int* in_sizes, int n_in,
                              void* d_out, int out_size)
{
    const float* query = (const float*)d_in[0];
    const float* ref   = (const float*)d_in[1];
    const float* toff  = (const float*)d_in[2];
    const float* inp   = (const float*)d_in[3];
    const float* Wv  = (const float*)d_in[6];
    const float* bv  = (const float*)d_in[7];
    const float* Ws  = (const float*)d_in[8];
    const float* bs  = (const float*)d_in[9];
    const float* Wa  = (const float*)d_in[10];
    const float* ba  = (const float*)d_in[11];
    const float* Wts = (const float*)d_in[12];
    const float* bts = (const float*)d_in[13];
    const float* Wta = (const float*)d_in[14];
    const float* bta = (const float*)d_in[15];
    const float* Wo  = (const float*)d_in[16];
    const float* bo  = (const float*)d_in[17];

    float* proj  = sym_addr(g_proj);
    float* value = sym_addr(g_value);
    float* outh  = sym_addr(g_outh);

    proj_kernel<<<512, 256>>>(query, inp, Wv, bv, Ws, bs, Wa, ba,
                              Wts, bts, Wta, bta, proj, value);

    sample_kernel<<<LQ, 256>>>(ref, toff, proj, value, outh);

    out_kernel<<<256, 256>>>(outh, Wo, bo, (float*)d_out);
}

// round 4
// speedup vs baseline: 1.3459x; 1.0070x over previous
#include <cuda_runtime.h>
#include <cuda_bf16.h>
#include <math.h>

// ---------------------------------------------------------------------------
// Problem constants
// ---------------------------------------------------------------------------
#define LQ      8160
#define DMODEL  256

__constant__ int c_lstart[4] = {0, 6144, 7680, 8064};

// ---------------------------------------------------------------------------
// Scratch (device globals; no allocation allowed)
// ---------------------------------------------------------------------------
__device__ float g_proj  [LQ * 768];
__device__ float g_value [LQ * DMODEL];
__device__ float g_outh  [LQ * DMODEL];

union F2U { float f[2]; unsigned long long u; };

// ---------------------------------------------------------------------------
// Double-buffered SGEMM tile using packed fp32x2 FMA (FFMA2).
// C[*,128] = A[M,256] @ B[256,128] + bias. BN=128, BK=16, 256 threads, TN=8.
// ---------------------------------------------------------------------------
template<int BM_, int TM_>
__device__ __forceinline__ void gemm_tile(
    const float* __restrict__ A,
    const float* __restrict__ B, int ldb,
    const float* __restrict__ bias,
    float* __restrict__ C, int ldc,
    int mt)
{
    constexpr int BN_ = 128, BK_ = 16, TN_ = 8;
    constexpr int APASS = BM_ / 64;
    constexpr int KTILES = 256 / BK_;   // 16

    __shared__ float As[2][BK_][BM_];
    __shared__ float Bs[2][BK_][BN_];

    const int tid  = threadIdx.x;
    const int trow = tid >> 4;          // 0..15
    const int tcol = tid & 15;          // 0..15
    const int aRow = tid >> 2;          // 0..63
    const int aCol = (tid & 3) << 2;    // 0,4,8,12
    const int bRow = tid >> 5;          // 0..7
    const int bCol = (tid & 31) << 2;   // 0..124

    float4 aP[APASS], bP[2];

    #pragma unroll
    for (int p = 0; p < APASS; p++) {
        const int r  = aRow + p * 64;
        const int gr = mt * BM_ + r;
        float4 v = make_float4(0.f, 0.f, 0.f, 0.f);
        if (gr < LQ) v = *(const float4*)(A + (size_t)gr * 256 + aCol);
        As[0][aCol + 0][r] = v.x; As[0][aCol + 1][r] = v.y;
        As[0][aCol + 2][r] = v.z; As[0][aCol + 3][r] = v.w;
    }
    #pragma unroll
    for (int p = 0; p < 2; p++)
        *(float4*)&Bs[0][bRow + p * 8][bCol] =
            *(const float4*)(B + (size_t)(bRow + p * 8) * ldb + bCol);
    __syncthreads();

    // packed accumulators: TM_ x (TN_/2) f32x2 lanes; 0ull == (0.f, 0.f)
    unsigned long long acc2[TM_][TN_ / 2];
    #pragma unroll
    for (int i = 0; i < TM_; i++)
        #pragma unroll
        for (int j = 0; j < TN_ / 2; j++) acc2[i][j] = 0ull;

    int buf = 0;
    for (int t = 0; t < KTILES; t++) {
        const int nk = t + 1;
        if (nk < KTILES) {
            const int k0 = nk * BK_;
            #pragma unroll
            for (int p = 0; p < APASS; p++) {
                const int gr = mt * BM_ + aRow + p * 64;
                aP[p] = make_float4(0.f, 0.f, 0.f, 0.f);
                if (gr < LQ) aP[p] = *(const float4*)(A + (size_t)gr * 256 + k0 + aCol);
            }
            #pragma unroll
            for (int p = 0; p < 2; p++)
                bP[p] = *(const float4*)(B + (size_t)(k0 + bRow + p * 8) * ldb + bCol);
        }
        #pragma unroll
        for (int k = 0; k < BK_; k++) {
            float ra[TM_];
            #pragma unroll
            for (int i = 0; i < TM_; i += 4)
                *(float4*)&ra[i] = *(const float4*)&As[buf][k][trow * TM_ + i];

            // B pairs as packed f32x2 (adjacent columns)
            unsigned long long rb2[TN_ / 2];
            {
                float4 b0 = *(const float4*)&Bs[buf][k][tcol * TN_ + 0];
                float4 b1 = *(const float4*)&Bs[buf][k][tcol * TN_ + 4];
                F2U u;
                u.f[0] = b0.x; u.f[1] = b0.y; rb2[0] = u.u;
                u.f[0] = b0.z; u.f[1] = b0.w; rb2[1] = u.u;
                u.f[0] = b1.x; u.f[1] = b1.y; rb2[2] = u.u;
                u.f[0] = b1.z; u.f[1] = b1.w; rb2[3] = u.u;
            }
            #pragma unroll
            for (int i = 0; i < TM_; i++) {
                unsigned long long a2;
                asm("mov.b64 %0, {%1, %2};" : "=l"(a2) : "f"(ra[i]), "f"(ra[i]));
                #pragma unroll
                for (int j = 0; j < TN_ / 2; j++)
                    asm("fma.rn.f32x2 %0, %1, %2, %0;"
                        : "+l"(acc2[i][j]) : "l"(a2), "l"(rb2[j]));
            }
        }
        if (nk < KTILES) {
            const int nb = buf ^ 1;
            #pragma unroll
            for (int p = 0; p < APASS; p++) {
                const int r = aRow + p * 64;
                As[nb][aCol + 0][r] = aP[p].x; As[nb][aCol + 1][r] = aP[p].y;
                As[nb][aCol + 2][r] = aP[p].z; As[nb][aCol + 3][r] = aP[p].w;
            }
            #pragma unroll
            for (int p = 0; p < 2; p++)
                *(float4*)&Bs[nb][bRow + p * 8][bCol] = bP[p];
            __syncthreads();
            buf = nb;
        }
    }

    #pragma unroll
    for (int i = 0; i < TM_; i++) {
        const int r = mt * BM_ + trow * TM_ + i;
        if (r >= LQ) continue;
        #pragma unroll
        for (int j = 0; j < TN_; j += 4) {
            const int c = tcol * TN_ + j;
            F2U lo, hi;
            lo.u = acc2[i][j / 2];
            hi.u = acc2[i][j / 2 + 1];
            float4 v;
            v.x = lo.f[0] + bias[c + 0];
            v.y = lo.f[1] + bias[c + 1];
            v.z = hi.f[0] + bias[c + 2];
            v.w = hi.f[1] + bias[c + 3];
            *(float4*)(C + (size_t)r * ldc + c) = v;
        }
    }
}

// ---------------------------------------------------------------------------
// Fused projection GEMM (512 tiles, one launch)
// ---------------------------------------------------------------------------
__global__ __launch_bounds__(256, 2) void proj_kernel(
    const float* __restrict__ query, const float* __restrict__ inp,
    const float* __restrict__ Wv,  const float* __restrict__ bv,
    const float* __restrict__ Ws,  const float* __restrict__ bs,
    const float* __restrict__ Wa,  const float* __restrict__ ba,
    const float* __restrict__ Wts, const float* __restrict__ bts,
    const float* __restrict__ Wta, const float* __restrict__ bta,
    float* __restrict__ proj, float* __restrict__ value)
{
    const int t = blockIdx.x;
    const float *A, *B, *bias;
    float* C;
    int ldb, ldc, mt;

    if (t < 384) {
        mt = t / 6;
        const int nt = t % 6;
        A = query; ldc = 768; C = proj + nt * 128;
        switch (nt) {
            case 0:  B = Ws;        bias = bs;        ldb = 256; break;
            case 1:  B = Ws + 128;  bias = bs + 128;  ldb = 256; break;
            case 2:  B = Wa;        bias = ba;        ldb = 128; break;
            case 3:  B = Wts;       bias = bts;       ldb = 256; break;
            case 4:  B = Wts + 128; bias = bts + 128; ldb = 256; break;
            default: B = Wta;       bias = bta;       ldb = 128; break;
        }
    } else {
        const int u = t - 384;
        mt = u >> 1;
        const int nt = u & 1;
        A = inp; B = Wv + nt * 128; bias = bv + nt * 128; ldb = 256;
        C = value + nt * 128; ldc = 256;
    }
    gemm_tile<128, 8>(A, B, ldb, bias, C, ldc, mt);
}

__global__ __launch_bounds__(256, 2) void out_kernel(
    const float* __restrict__ outh, const float* __restrict__ Wo,
    const float* __restrict__ bo, float* __restrict__ out)
{
    const int mt = blockIdx.x >> 1;
    const int nt = blockIdx.x & 1;
    gemm_tile<64, 4>(outh, Wo + nt * 128, 256, bo + nt * 128,
                     out + nt * 128, 256, mt);
}

// ---------------------------------------------------------------------------
// Sampling kernel: one warp per (q, head). Lane = channel d (0..31).
// ---------------------------------------------------------------------------
__global__ __launch_bounds__(256) void sample_kernel(
    const float* __restrict__ ref,
    const float* __restrict__ toff,
    const float* __restrict__ proj,
    const float* __restrict__ value,
    float* __restrict__ outh)
{
    __shared__ float sw[8][32];
    __shared__ float sx[8][32];
    __shared__ float sy[8][32];

    const int wid   = threadIdx.x >> 5;
    const int lane  = threadIdx.x & 31;
    const int wglob = blockIdx.x * 8 + wid;
    const int q     = wglob >> 3;
    const int head  = wglob & 7;

    const float* prow = proj + (size_t)q * 768;

    {
        const int p = lane;
        const int l = p >> 3;
        const int j = p & 7;
        const float Wl = (float)(48 >> l);
        const float Hl = (float)(128 >> l);

        const float refx = ref[q * 8 + l * 2 + 0];
        const float refy = ref[q * 8 + l * 2 + 1];

        float lg, lx, ly;
        if (j < 4) {
            lg = prow[256 + head * 16 + l * 4 + j];
            const float ox = prow[head * 32 + l * 8 + j * 2 + 0];
            const float oy = prow[head * 32 + l * 8 + j * 2 + 1];
            lx = refx + ox / Wl;
            ly = refy + oy / Hl;
        } else {
            const int kk = j - 4;
            const int tw = kk >> 1;
            lg = prow[640 + head * 16 + l * 4 + kk];
            const float ox = prow[384 + head * 32 + l * 8 + kk * 2 + 0];
            const float oy = prow[384 + head * 32 + l * 8 + kk * 2 + 1];
            const float tx = toff[q * 16 + l * 4 + tw * 2 + 0];
            const float ty = toff[q * 16 + l * 4 + tw * 2 + 1];
            lx = refx + tx + ox / Wl;
            ly = refy + ty + oy / Hl;
        }

        float m = lg;
        #pragma unroll
        for (int o = 16; o > 0; o >>= 1)
            m = fmaxf(m, __shfl_xor_sync(0xffffffffu, m, o));
        float e = expf(lg - m);
        float s = e;
        #pragma unroll
        for (int o = 16; o > 0; o >>= 1)
            s += __shfl_xor_sync(0xffffffffu, s, o);

        sw[wid][p] = e / s;
        sx[wid][p] = lx * Wl - 0.5f;
        sy[wid][p] = ly * Hl - 0.5f;
    }
    __syncwarp();

    const int d = lane;
    float acc = 0.f;

    #pragma unroll 8
    for (int p = 0; p < 32; p++) {
        const int l  = p >> 3;
        const int W  = 48 >> l;
        const int H  = 128 >> l;
        const int st = c_lstart[l];

        const float wgt = sw[wid][p];
        const float gx  = sx[wid][p];
        const float gy  = sy[wid][p];

        const float fx0 = floorf(gx), fy0 = floorf(gy);
        const int ix0 = (int)fx0, iy0 = (int)fy0;
        const int ix1 = ix0 + 1,  iy1 = iy0 + 1;
        const float wx = gx - fx0, wy = gy - fy0;

        const bool vx0 = (ix0 >= 0) & (ix0 < W);
        const bool vx1 = (ix1 >= 0) & (ix1 < W);
        const bool vy0 = (iy0 >= 0) & (iy0 < H);
        const bool vy1 = (iy1 >= 0) & (iy1 < H);

        const float* base = value + (size_t)st * 256 + head * 32 + d;

        const float v00 = (vx0 & vy0) ? base[(iy0 * W + ix0) * 256] : 0.f;
        const float v10 = (vx1 & vy0) ? base[(iy0 * W + ix1) * 256] : 0.f;
        const float v01 = (vx0 & vy1) ? base[(iy1 * W + ix0) * 256] : 0.f;
        const float v11 = (vx1 & vy1) ? base[(iy1 * W + ix1) * 256] : 0.f;

        const float bil = v00 * (1.f - wx) * (1.f - wy)
                        + v10 * wx * (1.f - wy)
                        + v01 * (1.f - wx) * wy
                        + v11 * wx * wy;
        acc = fmaf(wgt, bil, acc);
    }

    outh[q * 256 + head * 32 + d] = acc;
}

// ---------------------------------------------------------------------------
// Launch
// ---------------------------------------------------------------------------
static float* sym_addr(const void* sym)
{
    void* p = nullptr;
    cudaGetSymbolAddress(&p, sym);
    return (float*)p;
}

extern "C" void kernel_launch(void* const* d_in, const int* in_sizes, int n_in,
                              void* d_out, int out_size)
{
    const float* query = (const float*)d_in[0];
    const float* ref   = (const float*)d_in[1];
    const float* toff  = (const float*)d_in[2];
    const float* inp   = (const float*)d_in[3];
    const float* Wv  = (const float*)d_in[6];
    const float* bv  = (const float*)d_in[7];
    const float* Ws  = (const float*)d_in[8];
    const float* bs  = (const float*)d_in[9];
    const float* Wa  = (const float*)d_in[10];
    const float* ba  = (const float*)d_in[11];
    const float* Wts = (const float*)d_in[12];
    const float* bts = (const float*)d_in[13];
    const float* Wta = (const float*)d_in[14];
    const float* bta = (const float*)d_in[15];
    const float* Wo  = (const float*)d_in[16];
    const float* bo  = (const float*)d_in[17];

    float* proj  = sym_addr(g_proj);
    float* value = sym_addr(g_value);
    float* outh  = sym_addr(g_outh);

    proj_kernel<<<512, 256>>>(query, inp, Wv, bv, Ws, bs, Wa, ba,
                              Wts, bts, Wta, bta, proj, value);

    sample_kernel<<<LQ, 256>>>(ref, toff, proj, value, outh);

    out_kernel<<<256, 256>>>(outh, Wo, bo, (float*)d_out);
}

// round 5
// speedup vs baseline: 1.6303x; 1.2113x over previous
#include <cuda_runtime.h>
#include <cuda_fp16.h>
#include <cuda_bf16.h>
#include <math.h>

// ---------------------------------------------------------------------------
// Problem constants
// ---------------------------------------------------------------------------
#define LQ      8160
#define DMODEL  256

__constant__ int c_lstart[4] = {0, 6144, 7680, 8064};

// ---------------------------------------------------------------------------
// Scratch (device globals; no allocation allowed)
// ---------------------------------------------------------------------------
__device__ float  g_proj   [LQ * 768];
__device__ __half g_value_h[LQ * DMODEL];
__device__ float  g_outh   [LQ * DMODEL];

// ---------------------------------------------------------------------------
// bf16 helpers
// ---------------------------------------------------------------------------
__device__ __forceinline__ unsigned pack2bf(float x, float y)
{
    __nv_bfloat162 t = __floats2bfloat162_rn(x, y);   // x -> low half
    return *reinterpret_cast<unsigned*>(&t);
}

__device__ __forceinline__ void mma_bf16(float* d, const unsigned* a, const unsigned* b)
{
    asm volatile(
        "mma.sync.aligned.m16n8k16.row.col.f32.bf16.bf16.f32 "
        "{%0,%1,%2,%3}, {%4,%5,%6,%7}, {%8,%9}, {%0,%1,%2,%3};"
        : "+f"(d[0]), "+f"(d[1]), "+f"(d[2]), "+f"(d[3])
        : "r"(a[0]), "r"(a[1]), "r"(a[2]), "r"(a[3]),
          "r"(b[0]), "r"(b[1]));
}

// ---------------------------------------------------------------------------
// Tensor-core GEMM tile (bf16 3-pass split, fp32-quality):
//   C[128-tile rows, 128 cols] = A[M,256] @ B[256,128] + bias
// A row-major lda=256. B row-major (ldb given), pre-offset to col tile.
// smem: k-pairs packed into u32 words; strides padded for conflict-free LDS.
// 256 threads = 8 warps as 4(m) x 2(n); each warp 32x64 via m16n8k16 atoms.
// ---------------------------------------------------------------------------
struct GemmSmem {
    unsigned Ah[128][20];   // [m][k/2]  (16 used cols, pad->20)
    unsigned Al[128][20];
    unsigned Bh[16][136];   // [k/2][n]  (128 used cols, pad->136)
    unsigned Bl[16][136];
};

template<typename OutT>
__device__ __forceinline__ void gemm_mma(
    GemmSmem* sm,
    const float* __restrict__ A,
    const float* __restrict__ B, int ldb,
    const float* __restrict__ bias,
    OutT* __restrict__ C, int ldc,
    int mt)
{
    const int tid  = threadIdx.x;
    const int wid  = tid >> 5;
    const int lane = tid & 31;
    const int g    = lane >> 2;       // 0..7
    const int cq   = lane & 3;        // 0..3
    const int wm   = wid >> 1;        // 0..3 -> m base wm*32
    const int wn   = wid & 1;         // 0..1 -> n base wn*64

    // A loader mapping: row = tid>>1 (0..127), half = tid&1 -> k cols 16h..16h+15
    const int aRow  = tid >> 1;
    const int aHalf = tid & 1;
    // B loader mapping: pair = tid>>4 (0..15), n0 = (tid&15)*8
    const int bPair = tid >> 4;
    const int bN0   = (tid & 15) * 8;

    float acc[2][8][4];
    #pragma unroll
    for (int i = 0; i < 2; i++)
        #pragma unroll
        for (int j = 0; j < 8; j++)
            #pragma unroll
            for (int v = 0; v < 4; v++) acc[i][j][v] = 0.f;

    for (int ck = 0; ck < 8; ck++) {
        const int k0 = ck * 32;

        // ---- load + split A chunk: rows 0..127, k cols k0..k0+31 ----
        {
            const int gr = mt * 128 + aRow;
            const float* src = A + (size_t)gr * 256 + k0 + 16 * aHalf;
            #pragma unroll
            for (int j = 0; j < 4; j++) {
                float4 v = make_float4(0.f, 0.f, 0.f, 0.f);
                if (gr < LQ) v = *(const float4*)(src + 4 * j);
                float hx = __bfloat162float(__float2bfloat16_rn(v.x));
                float hy = __bfloat162float(__float2bfloat16_rn(v.y));
                float hz = __bfloat162float(__float2bfloat16_rn(v.z));
                float hw = __bfloat162float(__float2bfloat16_rn(v.w));
                const int wc = 8 * aHalf + 2 * j;
                sm->Ah[aRow][wc + 0] = pack2bf(hx, hy);
                sm->Ah[aRow][wc + 1] = pack2bf(hz, hw);
                sm->Al[aRow][wc + 0] = pack2bf(v.x - hx, v.y - hy);
                sm->Al[aRow][wc + 1] = pack2bf(v.z - hz, v.w - hw);
            }
        }

        // ---- load + split B chunk: k rows k0..k0+31, n 0..127 (pair-packed) ----
        {
            const float* r0 = B + (size_t)(k0 + 2 * bPair)     * ldb + bN0;
            const float* r1 = B + (size_t)(k0 + 2 * bPair + 1) * ldb + bN0;
            float4 a0 = *(const float4*)(r0 + 0);
            float4 a1 = *(const float4*)(r0 + 4);
            float4 b0 = *(const float4*)(r1 + 0);
            float4 b1 = *(const float4*)(r1 + 4);
            const float e0[8] = {a0.x, a0.y, a0.z, a0.w, a1.x, a1.y, a1.z, a1.w};
            const float e1[8] = {b0.x, b0.y, b0.z, b0.w, b1.x, b1.y, b1.z, b1.w};
            #pragma unroll
            for (int j = 0; j < 8; j++) {
                float h0 = __bfloat162float(__float2bfloat16_rn(e0[j]));
                float h1 = __bfloat162float(__float2bfloat16_rn(e1[j]));
                sm->Bh[bPair][bN0 + j] = pack2bf(h0, h1);
                sm->Bl[bPair][bN0 + j] = pack2bf(e0[j] - h0, e1[j] - h1);
            }
        }

        __syncthreads();

        // ---- compute: 2 k16 sub-tiles ----
        #pragma unroll
        for (int kt = 0; kt < 2; kt++) {
            unsigned afh[2][4], afl[2][4];
            #pragma unroll
            for (int m2 = 0; m2 < 2; m2++) {
                const int r = wm * 32 + m2 * 16 + g;
                const int wc = 8 * kt + cq;
                afh[m2][0] = sm->Ah[r][wc];       afh[m2][1] = sm->Ah[r + 8][wc];
                afh[m2][2] = sm->Ah[r][wc + 4];   afh[m2][3] = sm->Ah[r + 8][wc + 4];
                afl[m2][0] = sm->Al[r][wc];       afl[m2][1] = sm->Al[r + 8][wc];
                afl[m2][2] = sm->Al[r][wc + 4];   afl[m2][3] = sm->Al[r + 8][wc + 4];
            }
            #pragma unroll
            for (int nt = 0; nt < 8; nt++) {
                const int n = wn * 64 + nt * 8 + g;
                unsigned bfh[2], bfl[2];
                bfh[0] = sm->Bh[8 * kt + cq][n];
                bfh[1] = sm->Bh[8 * kt + cq + 4][n];
                bfl[0] = sm->Bl[8 * kt + cq][n];
                bfl[1] = sm->Bl[8 * kt + cq + 4][n];
                #pragma unroll
                for (int m2 = 0; m2 < 2; m2++) {
                    mma_bf16(acc[m2][nt], afh[m2], bfh);
                    mma_bf16(acc[m2][nt], afh[m2], bfl);
                    mma_bf16(acc[m2][nt], afl[m2], bfh);
                }
            }
        }

        __syncthreads();
    }

    // ---- epilogue ----
    #pragma unroll
    for (int m2 = 0; m2 < 2; m2++) {
        const int r0 = mt * 128 + wm * 32 + m2 * 16 + g;
        const int r1 = r0 + 8;
        #pragma unroll
        for (int nt = 0; nt < 8; nt++) {
            const int cb = wn * 64 + nt * 8 + 2 * cq;
            const float b0 = bias[cb], b1 = bias[cb + 1];
            if (r0 < LQ) {
                C[(size_t)r0 * ldc + cb]     = (OutT)(acc[m2][nt][0] + b0);
                C[(size_t)r0 * ldc + cb + 1] = (OutT)(acc[m2][nt][1] + b1);
            }
            if (r1 < LQ) {
                C[(size_t)r1 * ldc + cb]     = (OutT)(acc[m2][nt][2] + b0);
                C[(size_t)r1 * ldc + cb + 1] = (OutT)(acc[m2][nt][3] + b1);
            }
        }
    }
}

// ---------------------------------------------------------------------------
// Fused projection GEMM: 512 tiles
//   [0,384):   query @ {Ws,Wa,Wts,Wta} -> g_proj (fp32, ldc=768)
//   [384,512): input_flatten @ Wv      -> g_value_h (fp16, ldc=256)
// ---------------------------------------------------------------------------
__global__ __launch_bounds__(256, 2) void proj_kernel(
    const float* __restrict__ query, const float* __restrict__ inp,
    const float* __restrict__ Wv,  const float* __restrict__ bv,
    const float* __restrict__ Ws,  const float* __restrict__ bs,
    const float* __restrict__ Wa,  const float* __restrict__ ba,
    const float* __restrict__ Wts, const float* __restrict__ bts,
    const float* __restrict__ Wta, const float* __restrict__ bta,
    float* __restrict__ proj, __half* __restrict__ value)
{
    __shared__ GemmSmem sm;
    const int t = blockIdx.x;

    if (t < 384) {
        const int mt = t / 6;
        const int nt = t % 6;
        const float *B, *bias;
        int ldb;
        switch (nt) {
            case 0:  B = Ws;        bias = bs;        ldb = 256; break;
            case 1:  B = Ws + 128;  bias = bs + 128;  ldb = 256; break;
            case 2:  B = Wa;        bias = ba;        ldb = 128; break;
            case 3:  B = Wts;       bias = bts;       ldb = 256; break;
            case 4:  B = Wts + 128; bias = bts + 128; ldb = 256; break;
            default: B = Wta;       bias = bta;       ldb = 128; break;
        }
        gemm_mma<float>(&sm, query, B, ldb, bias, proj + nt * 128, 768, mt);
    } else {
        const int u = t - 384;
        const int mt = u >> 1;
        const int nt = u & 1;
        gemm_mma<__half>(&sm, inp, Wv + nt * 128, 256, bv + nt * 128,
                         value + nt * 128, 256, mt);
    }
}

__global__ __launch_bounds__(256, 2) void out_kernel(
    const float* __restrict__ outh, const float* __restrict__ Wo,
    const float* __restrict__ bo, float* __restrict__ out)
{
    __shared__ GemmSmem sm;
    const int mt = blockIdx.x >> 1;
    const int nt = blockIdx.x & 1;
    gemm_mma<float>(&sm, outh, Wo + nt * 128, 256, bo + nt * 128,
                    out + nt * 128, 256, mt);
}

// ---------------------------------------------------------------------------
// Sampling kernel: one warp per (q, head). Lane = channel d (0..31).
// value now fp16 -> 64B per tap per warp.
// ---------------------------------------------------------------------------
__global__ __launch_bounds__(256) void sample_kernel(
    const float* __restrict__ ref,
    const float* __restrict__ toff,
    const float* __restrict__ proj,
    const __half* __restrict__ value,
    float* __restrict__ outh)
{
    __shared__ float sw[8][32];
    __shared__ float sx[8][32];
    __shared__ float sy[8][32];

    const int wid   = threadIdx.x >> 5;
    const int lane  = threadIdx.x & 31;
    const int wglob = blockIdx.x * 8 + wid;
    const int q     = wglob >> 3;
    const int head  = wglob & 7;

    const float* prow = proj + (size_t)q * 768;

    {
        const int p = lane;
        const int l = p >> 3;
        const int j = p & 7;
        const float Wl = (float)(48 >> l);
        const float Hl = (float)(128 >> l);

        const float refx = ref[q * 8 + l * 2 + 0];
        const float refy = ref[q * 8 + l * 2 + 1];

        float lg, lx, ly;
        if (j < 4) {
            lg = prow[256 + head * 16 + l * 4 + j];
            const float ox = prow[head * 32 + l * 8 + j * 2 + 0];
            const float oy = prow[head * 32 + l * 8 + j * 2 + 1];
            lx = refx + ox / Wl;
            ly = refy + oy / Hl;
        } else {
            const int kk = j - 4;
            const int tw = kk >> 1;
            lg = prow[640 + head * 16 + l * 4 + kk];
            const float ox = prow[384 + head * 32 + l * 8 + kk * 2 + 0];
            const float oy = prow[384 + head * 32 + l * 8 + kk * 2 + 1];
            const float tx = toff[q * 16 + l * 4 + tw * 2 + 0];
            const float ty = toff[q * 16 + l * 4 + tw * 2 + 1];
            lx = refx + tx + ox / Wl;
            ly = refy + ty + oy / Hl;
        }

        float m = lg;
        #pragma unroll
        for (int o = 16; o > 0; o >>= 1)
            m = fmaxf(m, __shfl_xor_sync(0xffffffffu, m, o));
        float e = expf(lg - m);
        float s = e;
        #pragma unroll
        for (int o = 16; o > 0; o >>= 1)
            s += __shfl_xor_sync(0xffffffffu, s, o);

        sw[wid][p] = e / s;
        sx[wid][p] = lx * Wl - 0.5f;
        sy[wid][p] = ly * Hl - 0.5f;
    }
    __syncwarp();

    const int d = lane;
    float acc = 0.f;

    #pragma unroll 8
    for (int p = 0; p < 32; p++) {
        const int l  = p >> 3;
        const int W  = 48 >> l;
        const int H  = 128 >> l;
        const int st = c_lstart[l];

        const float wgt = sw[wid][p];
        const float gx  = sx[wid][p];
        const float gy  = sy[wid][p];

        const float fx0 = floorf(gx), fy0 = floorf(gy);
        const int ix0 = (int)fx0, iy0 = (int)fy0;
        const int ix1 = ix0 + 1,  iy1 = iy0 + 1;
        const float wx = gx - fx0, wy = gy - fy0;

        const bool vx0 = (ix0 >= 0) & (ix0 < W);
        const bool vx1 = (ix1 >= 0) & (ix1 < W);
        const bool vy0 = (iy0 >= 0) & (iy0 < H);
        const bool vy1 = (iy1 >= 0) & (iy1 < H);

        const __half* base = value + (size_t)st * 256 + head * 32 + d;

        const float v00 = (vx0 & vy0) ? __half2float(base[(iy0 * W + ix0) * 256]) : 0.f;
        const float v10 = (vx1 & vy0) ? __half2float(base[(iy0 * W + ix1) * 256]) : 0.f;
        const float v01 = (vx0 & vy1) ? __half2float(base[(iy1 * W + ix0) * 256]) : 0.f;
        const float v11 = (vx1 & vy1) ? __half2float(base[(iy1 * W + ix1) * 256]) : 0.f;

        const float bil = v00 * (1.f - wx) * (1.f - wy)
                        + v10 * wx * (1.f - wy)
                        + v01 * (1.f - wx) * wy
                        + v11 * wx * wy;
        acc = fmaf(wgt, bil, acc);
    }

    outh[q * 256 + head * 32 + d] = acc;
}

// ---------------------------------------------------------------------------
// Launch
// ---------------------------------------------------------------------------
static void* sym_addr(const void* sym)
{
    void* p = nullptr;
    cudaGetSymbolAddress(&p, sym);
    return p;
}

extern "C" void kernel_launch(void* const* d_in, const int* in_sizes, int n_in,
                              void* d_out, int out_size)
{
    const float* query = (const float*)d_in[0];
    const float* ref   = (const float*)d_in[1];
    const float* toff  = (const float*)d_in[2];
    const float* inp   = (const float*)d_in[3];
    const float* Wv  = (const float*)d_in[6];
    const float* bv  = (const float*)d_in[7];
    const float* Ws  = (const float*)d_in[8];
    const float* bs  = (const float*)d_in[9];
    const float* Wa  = (const float*)d_in[10];
    const float* ba  = (const float*)d_in[11];
    const float* Wts = (const float*)d_in[12];
    const float* bts = (const float*)d_in[13];
    const float* Wta = (const float*)d_in[14];
    const float* bta = (const float*)d_in[15];
    const float* Wo  = (const float*)d_in[16];
    const float* bo  = (const float*)d_in[17];

    float*  proj  = (float*)sym_addr(g_proj);
    __half* value = (__half*)sym_addr(g_value_h);
    float*  outh  = (float*)sym_addr(g_outh);

    proj_kernel<<<512, 256>>>(query, inp, Wv, bv, Ws, bs, Wa, ba,
                              Wts, bts, Wta, bta, proj, value);

    sample_kernel<<<LQ, 256>>>(ref, toff, proj, value, outh);

    out_kernel<<<128, 256>>>(outh, Wo, bo, (float*)d_out);
}

// round 6
// speedup vs baseline: 2.6978x; 1.6548x over previous
#include <cuda_runtime.h>
#include <cuda_fp16.h>
#include <cuda_bf16.h>
#include <math.h>

// ---------------------------------------------------------------------------
// Problem constants
// ---------------------------------------------------------------------------
#define LQ      8160
#define DMODEL  256

__constant__ int c_lstart[4] = {0, 6144, 7680, 8064};

typedef unsigned int uint;

// ---------------------------------------------------------------------------
// Scratch (device globals; no allocation allowed)
// ---------------------------------------------------------------------------
// Packed bf16x2 words. A-side: [row][kp] kp=0..127 (k-pair along K=256).
// B-side: [kp][n] (pair across k rows).
__device__ uint g_qh [LQ * 128], g_ql [LQ * 128];   // query hi/lo
__device__ uint g_ih [LQ * 128], g_il [LQ * 128];   // input_flatten hi/lo
__device__ uint g_oh [LQ * 128], g_ol [LQ * 128];   // sampled out hi/lo (packed by sample)
__device__ uint g_Wsh [128 * 256], g_Wsl [128 * 256];
__device__ uint g_Wtsh[128 * 256], g_Wtsl[128 * 256];
__device__ uint g_Wvh [128 * 256], g_Wvl [128 * 256];
__device__ uint g_Woh [128 * 256], g_Wol [128 * 256];
__device__ uint g_Wah [128 * 128], g_Wal [128 * 128];
__device__ uint g_Wtah[128 * 128], g_Wtal[128 * 128];

__device__ float  g_proj   [LQ * 768];
__device__ __half g_value_h[LQ * DMODEL];

// ---------------------------------------------------------------------------
// helpers
// ---------------------------------------------------------------------------
__device__ __forceinline__ uint pack2bf(float x, float y)
{
    __nv_bfloat162 t = __floats2bfloat162_rn(x, y);   // x -> low half
    return *reinterpret_cast<uint*>(&t);
}

__device__ __forceinline__ void split2(float f0, float f1, uint& hi, uint& lo)
{
    float h0 = __bfloat162float(__float2bfloat16_rn(f0));
    float h1 = __bfloat162float(__float2bfloat16_rn(f1));
    hi = pack2bf(h0, h1);
    lo = pack2bf(f0 - h0, f1 - h1);
}

__device__ __forceinline__ void mma_bf16(float* d, const uint* a, const uint* b)
{
    asm volatile(
        "mma.sync.aligned.m16n8k16.row.col.f32.bf16.bf16.f32 "
        "{%0,%1,%2,%3}, {%4,%5,%6,%7}, {%8,%9}, {%0,%1,%2,%3};"
        : "+f"(d[0]), "+f"(d[1]), "+f"(d[2]), "+f"(d[3])
        : "r"(a[0]), "r"(a[1]), "r"(a[2]), "r"(a[3]),
          "r"(b[0]), "r"(b[1]));
}

__device__ __forceinline__ void cpa16(void* dst_smem, const void* src, bool valid)
{
    uint ds = (uint)__cvta_generic_to_shared(dst_smem);
    int sz = valid ? 16 : 0;
    asm volatile("cp.async.cg.shared.global [%0], [%1], 16, %2;"
                 :: "r"(ds), "l"(src), "r"(sz));
}
#define CPA_COMMIT()  asm volatile("cp.async.commit_group;")
#define CPA_WAIT(n)   asm volatile("cp.async.wait_group %0;" :: "n"(n))

// ---------------------------------------------------------------------------
// Prep kernel: pack fp32 -> bf16 hi/lo words for A-side tensors and weights.
// ---------------------------------------------------------------------------
__global__ __launch_bounds__(256) void prep_kernel(
    const float* __restrict__ query, const float* __restrict__ inp,
    const float* __restrict__ Ws,  const float* __restrict__ Wa,
    const float* __restrict__ Wts, const float* __restrict__ Wta,
    const float* __restrict__ Wv,  const float* __restrict__ Wo)
{
    const int b = blockIdx.x;
    const int tid = threadIdx.x;

    if (b < 8160) {                 // A packs: query then input (4080 blocks each)
        const bool isQ = (b < 4080);
        const int  bl  = isQ ? b : b - 4080;
        const int  idx = bl * 256 + tid;      // word index, < 1044480
        const int  r   = idx >> 7;
        const int  kp  = idx & 127;
        const float* src = (isQ ? query : inp) + (size_t)r * 256 + 2 * kp;
        uint hi, lo;
        split2(src[0], src[1], hi, lo);
        if (isQ) { g_qh[idx] = hi; g_ql[idx] = lo; }
        else     { g_ih[idx] = hi; g_il[idx] = lo; }
    } else {                        // B packs
        const int u = b - 8160;
        const float* src; uint *dh, *dl; int N; int bl;
        if      (u < 128) { src = Ws;  dh = g_Wsh;  dl = g_Wsl;  N = 256; bl = u; }
        else if (u < 256) { src = Wts; dh = g_Wtsh; dl = g_Wtsl; N = 256; bl = u - 128; }
        else if (u < 384) { src = Wv;  dh = g_Wvh;  dl = g_Wvl;  N = 256; bl = u - 256; }
        else if (u < 512) { src = Wo;  dh = g_Woh;  dl = g_Wol;  N = 256; bl = u - 384; }
        else if (u < 576) { src = Wa;  dh = g_Wah;  dl = g_Wal;  N = 128; bl = u - 512; }
        else              { src = Wta; dh = g_Wtah; dl = g_Wtal; N = 128; bl = u - 576; }
        const int idx = bl * 256 + tid;       // word index over [128][N]
        const int kp  = idx / N;
        const int n   = idx - kp * N;
        uint hi, lo;
        split2(src[(size_t)(2 * kp) * N + n], src[(size_t)(2 * kp + 1) * N + n], hi, lo);
        dh[idx] = hi; dl[idx] = lo;
    }
}

// ---------------------------------------------------------------------------
// GEMM tile (bf16 3-pass, packed inputs, cp.async double-buffered):
//   C[128 rows, 128 cols] = A[M,256] @ B[256,128-tile] + bias
// ---------------------------------------------------------------------------
struct GemmSmem {
    uint Ah[128][20];   // [m][k-word]  16 used, pad->20
    uint Al[128][20];
    uint Bh[16][136];   // [k-pair][n]  128 used, pad->136
    uint Bl[16][136];
};

template<typename OutT>
__device__ __forceinline__ void gemm_mma(
    const uint* __restrict__ Ahg, const uint* __restrict__ Alg,
    const uint* __restrict__ Bhg, const uint* __restrict__ Blg, int ldbw,
    const float* __restrict__ bias,
    OutT* __restrict__ C, int ldc,
    int mt)
{
    extern __shared__ GemmSmem bufs[];

    const int tid  = threadIdx.x;
    const int wid  = tid >> 5;
    const int lane = tid & 31;
    const int g    = lane >> 2;
    const int cq   = lane & 3;
    const int wm   = wid >> 1;
    const int wn   = wid & 1;

    const int aRow  = tid >> 1;
    const int aHalf = tid & 1;
    const int bPair = tid >> 4;
    const int bN0   = (tid & 15) * 8;

    const bool  aValid = (mt * 128 + aRow) < LQ;
    const size_t aBase = (size_t)(aValid ? (mt * 128 + aRow) : 0) * 128;

    float acc[2][8][4];
    #pragma unroll
    for (int i = 0; i < 2; i++)
        #pragma unroll
        for (int j = 0; j < 8; j++)
            #pragma unroll
            for (int v = 0; v < 4; v++) acc[i][j][v] = 0.f;

    auto issue = [&](int ck, int bsel) {
        GemmSmem& s = bufs[bsel];
        const uint* ah = Ahg + aBase + ck * 16 + 8 * aHalf;
        const uint* al = Alg + aBase + ck * 16 + 8 * aHalf;
        cpa16(&s.Ah[aRow][8 * aHalf],     ah,     aValid);
        cpa16(&s.Ah[aRow][8 * aHalf + 4], ah + 4, aValid);
        cpa16(&s.Al[aRow][8 * aHalf],     al,     aValid);
        cpa16(&s.Al[aRow][8 * aHalf + 4], al + 4, aValid);
        const uint* bh = Bhg + (size_t)(ck * 16 + bPair) * ldbw + bN0;
        const uint* bl = Blg + (size_t)(ck * 16 + bPair) * ldbw + bN0;
        cpa16(&s.Bh[bPair][bN0],     bh,     true);
        cpa16(&s.Bh[bPair][bN0 + 4], bh + 4, true);
        cpa16(&s.Bl[bPair][bN0],     bl,     true);
        cpa16(&s.Bl[bPair][bN0 + 4], bl + 4, true);
        CPA_COMMIT();
    };

    issue(0, 0);
    int bsel = 0;

    for (int ck = 0; ck < 8; ck++) {
        if (ck < 7) { issue(ck + 1, bsel ^ 1); CPA_WAIT(1); }
        else        { CPA_WAIT(0); }
        __syncthreads();

        GemmSmem& s = bufs[bsel];
        #pragma unroll
        for (int kt = 0; kt < 2; kt++) {
            uint afh[2][4], afl[2][4];
            #pragma unroll
            for (int m2 = 0; m2 < 2; m2++) {
                const int r  = wm * 32 + m2 * 16 + g;
                const int wc = 8 * kt + cq;
                afh[m2][0] = s.Ah[r][wc];     afh[m2][1] = s.Ah[r + 8][wc];
                afh[m2][2] = s.Ah[r][wc + 4]; afh[m2][3] = s.Ah[r + 8][wc + 4];
                afl[m2][0] = s.Al[r][wc];     afl[m2][1] = s.Al[r + 8][wc];
                afl[m2][2] = s.Al[r][wc + 4]; afl[m2][3] = s.Al[r + 8][wc + 4];
            }
            #pragma unroll
            for (int nt = 0; nt < 8; nt++) {
                const int n = wn * 64 + nt * 8 + g;
                uint bfh[2], bfl[2];
                bfh[0] = s.Bh[8 * kt + cq][n];
                bfh[1] = s.Bh[8 * kt + cq + 4][n];
                bfl[0] = s.Bl[8 * kt + cq][n];
                bfl[1] = s.Bl[8 * kt + cq + 4][n];
                #pragma unroll
                for (int m2 = 0; m2 < 2; m2++) {
                    mma_bf16(acc[m2][nt], afh[m2], bfh);
                    mma_bf16(acc[m2][nt], afh[m2], bfl);
                    mma_bf16(acc[m2][nt], afl[m2], bfh);
                }
            }
        }
        __syncthreads();
        bsel ^= 1;
    }

    #pragma unroll
    for (int m2 = 0; m2 < 2; m2++) {
        const int r0 = mt * 128 + wm * 32 + m2 * 16 + g;
        const int r1 = r0 + 8;
        #pragma unroll
        for (int nt = 0; nt < 8; nt++) {
            const int cb = wn * 64 + nt * 8 + 2 * cq;
            const float b0 = bias[cb], b1 = bias[cb + 1];
            if (r0 < LQ) {
                C[(size_t)r0 * ldc + cb]     = (OutT)(acc[m2][nt][0] + b0);
                C[(size_t)r0 * ldc + cb + 1] = (OutT)(acc[m2][nt][1] + b1);
            }
            if (r1 < LQ) {
                C[(size_t)r1 * ldc + cb]     = (OutT)(acc[m2][nt][2] + b0);
                C[(size_t)r1 * ldc + cb + 1] = (OutT)(acc[m2][nt][3] + b1);
            }
        }
    }
}

// ---------------------------------------------------------------------------
// Fused projection GEMM: 512 tiles
// ---------------------------------------------------------------------------
__global__ __launch_bounds__(256, 2) void proj_kernel(
    const float* __restrict__ bs,  const float* __restrict__ ba,
    const float* __restrict__ bts, const float* __restrict__ bta,
    const float* __restrict__ bv)
{
    const int t = blockIdx.x;
    if (t < 384) {
        const int mt = t / 6;
        const int nt = t % 6;
        const uint *Bh, *Bl; const float* bias; int ldbw, off;
        switch (nt) {
            case 0:  Bh = g_Wsh;  Bl = g_Wsl;  bias = bs;        ldbw = 256; off = 0;   break;
            case 1:  Bh = g_Wsh;  Bl = g_Wsl;  bias = bs + 128;  ldbw = 256; off = 128; break;
            case 2:  Bh = g_Wah;  Bl = g_Wal;  bias = ba;        ldbw = 128; off = 0;   break;
            case 3:  Bh = g_Wtsh; Bl = g_Wtsl; bias = bts;       ldbw = 256; off = 0;   break;
            case 4:  Bh = g_Wtsh; Bl = g_Wtsl; bias = bts + 128; ldbw = 256; off = 128; break;
            default: Bh = g_Wtah; Bl = g_Wtal; bias = bta;       ldbw = 128; off = 0;   break;
        }
        gemm_mma<float>(g_qh, g_ql, Bh + off, Bl + off, ldbw, bias,
                        g_proj + nt * 128, 768, mt);
    } else {
        const int u = t - 384;
        const int mt = u >> 1;
        const int nt = u & 1;
        gemm_mma<__half>(g_ih, g_il, g_Wvh + nt * 128, g_Wvl + nt * 128, 256,
                         bv + nt * 128, g_value_h + nt * 128, 256, mt);
    }
}

__global__ __launch_bounds__(256, 2) void out_kernel(
    const float* __restrict__ bo, float* __restrict__ out)
{
    const int mt = blockIdx.x >> 1;
    const int nt = blockIdx.x & 1;
    gemm_mma<float>(g_oh, g_ol, g_Woh + nt * 128, g_Wol + nt * 128, 256,
                    bo + nt * 128, out + nt * 128, 256, mt);
}

// ---------------------------------------------------------------------------
// Sampling kernel: one warp per (q, head).
// Phase 1 (lane=p): compute fused weights + tap rows into smem.
// Phase 2: 2 points x 16 lanes, __half2 loads, combine via shfl.
// Writes packed bf16 hi/lo output words directly (GEMM A-layout).
// ---------------------------------------------------------------------------
__global__ __launch_bounds__(256) void sample_kernel(
    const float* __restrict__ ref,
    const float* __restrict__ toff)
{
    __shared__ int   s_row[8][32][4];
    __shared__ float s_w  [8][32][4];

    const int wid   = threadIdx.x >> 5;
    const int lane  = threadIdx.x & 31;
    const int q     = blockIdx.x;
    const int head  = wid;

    const float* prow = g_proj + (size_t)q * 768;

    // ---- setup: lane == point index p ----
    {
        const int p = lane;
        const int l = p >> 3;
        const int j = p & 7;
        const int W = 48 >> l;
        const int H = 128 >> l;
        const float Wl = (float)W;
        const float Hl = (float)H;

        const float refx = ref[q * 8 + l * 2 + 0];
        const float refy = ref[q * 8 + l * 2 + 1];

        float lg, lx, ly;
        if (j < 4) {
            lg = prow[256 + head * 16 + l * 4 + j];
            const float ox = prow[head * 32 + l * 8 + j * 2 + 0];
            const float oy = prow[head * 32 + l * 8 + j * 2 + 1];
            lx = refx + ox / Wl;
            ly = refy + oy / Hl;
        } else {
            const int kk = j - 4;
            const int tw = kk >> 1;
            lg = prow[640 + head * 16 + l * 4 + kk];
            const float ox = prow[384 + head * 32 + l * 8 + kk * 2 + 0];
            const float oy = prow[384 + head * 32 + l * 8 + kk * 2 + 1];
            const float tx = toff[q * 16 + l * 4 + tw * 2 + 0];
            const float ty = toff[q * 16 + l * 4 + tw * 2 + 1];
            lx = refx + tx + ox / Wl;
            ly = refy + ty + oy / Hl;
        }

        float m = lg;
        #pragma unroll
        for (int o = 16; o > 0; o >>= 1)
            m = fmaxf(m, __shfl_xor_sync(0xffffffffu, m, o));
        float e = expf(lg - m);
        float s = e;
        #pragma unroll
        for (int o = 16; o > 0; o >>= 1)
            s += __shfl_xor_sync(0xffffffffu, s, o);
        const float wgt = e / s;

        const float gx = lx * Wl - 0.5f;
        const float gy = ly * Hl - 0.5f;
        const float fx0 = floorf(gx), fy0 = floorf(gy);
        const int ix0 = (int)fx0, iy0 = (int)fy0;
        const int ix1 = ix0 + 1,  iy1 = iy0 + 1;
        const float wx = gx - fx0, wy = gy - fy0;

        const bool vx0 = (ix0 >= 0) & (ix0 < W);
        const bool vx1 = (ix1 >= 0) & (ix1 < W);
        const bool vy0 = (iy0 >= 0) & (iy0 < H);
        const bool vy1 = (iy1 >= 0) & (iy1 < H);

        const int st = c_lstart[l];
        s_row[wid][p][0] = (vx0 & vy0) ? st + iy0 * W + ix0 : -1;
        s_row[wid][p][1] = (vx1 & vy0) ? st + iy0 * W + ix1 : -1;
        s_row[wid][p][2] = (vx0 & vy1) ? st + iy1 * W + ix0 : -1;
        s_row[wid][p][3] = (vx1 & vy1) ? st + iy1 * W + ix1 : -1;
        s_w[wid][p][0] = wgt * (1.f - wx) * (1.f - wy);
        s_w[wid][p][1] = wgt * wx * (1.f - wy);
        s_w[wid][p][2] = wgt * (1.f - wx) * wy;
        s_w[wid][p][3] = wgt * wx * wy;
    }
    __syncwarp();

    // ---- accumulate: half-warp pp handles points 2*pb+pp, lane&15 = channel pair
    const int pp = lane >> 4;
    const int d2 = lane & 15;
    const __half2* base = (const __half2*)(g_value_h + head * 32 + 2 * d2);

    float ax = 0.f, ay = 0.f;
    #pragma unroll
    for (int pb = 0; pb < 16; pb++) {
        const int p = 2 * pb + pp;
        #pragma unroll
        for (int t = 0; t < 4; t++) {
            const int   r = s_row[wid][p][t];
            const float w = s_w[wid][p][t];
            if (r >= 0) {
                const __half2 v = base[(size_t)r * 128];
                const float2 f = __half22float2(v);
                ax = fmaf(w, f.x, ax);
                ay = fmaf(w, f.y, ay);
            }
        }
    }

    ax += __shfl_xor_sync(0xffffffffu, ax, 16);
    ay += __shfl_xor_sync(0xffffffffu, ay, 16);

    if (lane < 16) {
        uint hi, lo;
        split2(ax, ay, hi, lo);
        const int idx = q * 128 + head * 16 + d2;
        g_oh[idx] = hi;
        g_ol[idx] = lo;
    }
}

// ---------------------------------------------------------------------------
// Launch
// ---------------------------------------------------------------------------
extern "C" void kernel_launch(void* const* d_in, const int* in_sizes, int n_in,
                              void* d_out, int out_size)
{
    const float* query = (const float*)d_in[0];
    const float* ref   = (const float*)d_in[1];
    const float* toff  = (const float*)d_in[2];
    const float* inp   = (const float*)d_in[3];
    const float* Wv  = (const float*)d_in[6];
    const float* bv  = (const float*)d_in[7];
    const float* Ws  = (const float*)d_in[8];
    const float* bs  = (const float*)d_in[9];
    const float* Wa  = (const float*)d_in[10];
    const float* ba  = (const float*)d_in[11];
    const float* Wts = (const float*)d_in[12];
    const float* bts = (const float*)d_in[13];
    const float* Wta = (const float*)d_in[14];
    const float* bta = (const float*)d_in[15];
    const float* Wo  = (const float*)d_in[16];
    const float* bo  = (const float*)d_in[17];

    const int smem = 2 * (int)sizeof(GemmSmem);
    cudaFuncSetAttribute(proj_kernel, cudaFuncAttributeMaxDynamicSharedMemorySize, smem);
    cudaFuncSetAttribute(out_kernel,  cudaFuncAttributeMaxDynamicSharedMemorySize, smem);

    prep_kernel<<<8800, 256>>>(query, inp, Ws, Wa, Wts, Wta, Wv, Wo);

    proj_kernel<<<512, 256, smem>>>(bs, ba, bts, bta, bv);

    sample_kernel<<<LQ, 256>>>(ref, toff);

    out_kernel<<<128, 256, smem>>>(bo, (float*)d_out);
}

// round 7
// speedup vs baseline: 2.7641x; 1.0246x over previous
#include <cuda_runtime.h>
#include <cuda_fp16.h>
#include <cuda_bf16.h>
#include <math.h>

// ---------------------------------------------------------------------------
// Problem constants
// ---------------------------------------------------------------------------
#define LQ      8160
#define DMODEL  256

__constant__ int c_lstart[4] = {0, 6144, 7680, 8064};

typedef unsigned int uint;

// ---------------------------------------------------------------------------
// Scratch (device globals; no allocation allowed)
// ---------------------------------------------------------------------------
__device__ uint g_qh [LQ * 128], g_ql [LQ * 128];
__device__ uint g_ih [LQ * 128], g_il [LQ * 128];
__device__ uint g_oh [LQ * 128], g_ol [LQ * 128];
__device__ uint g_Wsh [128 * 256], g_Wsl [128 * 256];
__device__ uint g_Wtsh[128 * 256], g_Wtsl[128 * 256];
__device__ uint g_Wvh [128 * 256], g_Wvl [128 * 256];
__device__ uint g_Woh [128 * 256], g_Wol [128 * 256];
__device__ uint g_Wah [128 * 128], g_Wal [128 * 128];
__device__ uint g_Wtah[128 * 128], g_Wtal[128 * 128];

__device__ float  g_proj   [LQ * 768];
__device__ __half g_value_h[LQ * DMODEL];

// ---------------------------------------------------------------------------
// helpers
// ---------------------------------------------------------------------------
__device__ __forceinline__ uint pack2bf(float x, float y)
{
    __nv_bfloat162 t = __floats2bfloat162_rn(x, y);
    return *reinterpret_cast<uint*>(&t);
}

__device__ __forceinline__ void split2(float f0, float f1, uint& hi, uint& lo)
{
    float h0 = __bfloat162float(__float2bfloat16_rn(f0));
    float h1 = __bfloat162float(__float2bfloat16_rn(f1));
    hi = pack2bf(h0, h1);
    lo = pack2bf(f0 - h0, f1 - h1);
}

__device__ __forceinline__ void mma_bf16(float* d, const uint* a, const uint* b)
{
    asm volatile(
        "mma.sync.aligned.m16n8k16.row.col.f32.bf16.bf16.f32 "
        "{%0,%1,%2,%3}, {%4,%5,%6,%7}, {%8,%9}, {%0,%1,%2,%3};"
        : "+f"(d[0]), "+f"(d[1]), "+f"(d[2]), "+f"(d[3])
        : "r"(a[0]), "r"(a[1]), "r"(a[2]), "r"(a[3]),
          "r"(b[0]), "r"(b[1]));
}

__device__ __forceinline__ void cpa16(void* dst_smem, const void* src, bool valid)
{
    uint ds = (uint)__cvta_generic_to_shared(dst_smem);
    int sz = valid ? 16 : 0;
    asm volatile("cp.async.cg.shared.global [%0], [%1], 16, %2;"
                 :: "r"(ds), "l"(src), "r"(sz));
}
#define CPA_COMMIT()  asm volatile("cp.async.commit_group;")
#define CPA_WAIT(n)   asm volatile("cp.async.wait_group %0;" :: "n"(n))

// ---------------------------------------------------------------------------
// Prep kernel
// ---------------------------------------------------------------------------
__global__ __launch_bounds__(256) void prep_kernel(
    const float* __restrict__ query, const float* __restrict__ inp,
    const float* __restrict__ Ws,  const float* __restrict__ Wa,
    const float* __restrict__ Wts, const float* __restrict__ Wta,
    const float* __restrict__ Wv,  const float* __restrict__ Wo)
{
    const int b = blockIdx.x;
    const int tid = threadIdx.x;

    if (b < 8160) {
        const bool isQ = (b < 4080);
        const int  bl  = isQ ? b : b - 4080;
        const int  idx = bl * 256 + tid;
        const int  r   = idx >> 7;
        const int  kp  = idx & 127;
        const float* src = (isQ ? query : inp) + (size_t)r * 256 + 2 * kp;
        uint hi, lo;
        split2(src[0], src[1], hi, lo);
        if (isQ) { g_qh[idx] = hi; g_ql[idx] = lo; }
        else     { g_ih[idx] = hi; g_il[idx] = lo; }
    } else {
        const int u = b - 8160;
        const float* src; uint *dh, *dl; int N; int bl;
        if      (u < 128) { src = Ws;  dh = g_Wsh;  dl = g_Wsl;  N = 256; bl = u; }
        else if (u < 256) { src = Wts; dh = g_Wtsh; dl = g_Wtsl; N = 256; bl = u - 128; }
        else if (u < 384) { src = Wv;  dh = g_Wvh;  dl = g_Wvl;  N = 256; bl = u - 256; }
        else if (u < 512) { src = Wo;  dh = g_Woh;  dl = g_Wol;  N = 256; bl = u - 384; }
        else if (u < 576) { src = Wa;  dh = g_Wah;  dl = g_Wal;  N = 128; bl = u - 512; }
        else              { src = Wta; dh = g_Wtah; dl = g_Wtal; N = 128; bl = u - 576; }
        const int idx = bl * 256 + tid;
        const int kp  = idx / N;
        const int n   = idx - kp * N;
        uint hi, lo;
        split2(src[(size_t)(2 * kp) * N + n], src[(size_t)(2 * kp + 1) * N + n], hi, lo);
        dh[idx] = hi; dl[idx] = lo;
    }
}

// ---------------------------------------------------------------------------
// GEMM tile (bf16 3-pass, packed inputs, cp.async double-buffered)
// Templated on BM (64 or 128). 256 threads.
//   BM=128: warps 4(m) x 2(n), warp tile 32x64
//   BM=64 : warps 2(m) x 4(n), warp tile 32x32
// ---------------------------------------------------------------------------
template<int BM>
struct GemmSmemT {
    uint Ah[BM][20];
    uint Al[BM][20];
    uint Bh[16][136];
    uint Bl[16][136];
};

template<int BM, typename OutT>
__device__ __forceinline__ void gemm_mma(
    const uint* __restrict__ Ahg, const uint* __restrict__ Alg,
    const uint* __restrict__ Bhg, const uint* __restrict__ Blg, int ldbw,
    const float* __restrict__ bias,
    OutT* __restrict__ C, int ldc,
    int mt)
{
    constexpr int NT = (BM == 128) ? 8 : 4;       // n sub-tiles per warp
    constexpr int ALOOP = BM / 64;                // cpa16 per array per thread
    extern __shared__ char smem_raw[];
    GemmSmemT<BM>* bufs = reinterpret_cast<GemmSmemT<BM>*>(smem_raw);

    const int tid  = threadIdx.x;
    const int wid  = tid >> 5;
    const int lane = tid & 31;
    const int g    = lane >> 2;
    const int cq   = lane & 3;
    const int wm   = (BM == 128) ? (wid >> 1) : (wid >> 2);
    const int wn   = (BM == 128) ? (wid & 1)  : (wid & 3);

    const int bPair = tid >> 4;
    const int bN0   = (tid & 15) * 8;

    float acc[2][NT][4];
    #pragma unroll
    for (int i = 0; i < 2; i++)
        #pragma unroll
        for (int j = 0; j < NT; j++)
            #pragma unroll
            for (int v = 0; v < 4; v++) acc[i][j][v] = 0.f;

    auto issue = [&](int ck, int bsel) {
        GemmSmemT<BM>& s = bufs[bsel];
        #pragma unroll
        for (int i = 0; i < ALOOP; i++) {
            const int op  = i * 256 + tid;        // < BM*4
            const int row = op >> 2;
            const int wq  = (op & 3) * 4;
            const int gr  = mt * BM + row;
            const bool v  = gr < LQ;
            const size_t base = (size_t)(v ? gr : 0) * 128 + ck * 16 + wq;
            cpa16(&s.Ah[row][wq], Ahg + base, v);
            cpa16(&s.Al[row][wq], Alg + base, v);
        }
        const uint* bh = Bhg + (size_t)(ck * 16 + bPair) * ldbw + bN0;
        const uint* bl = Blg + (size_t)(ck * 16 + bPair) * ldbw + bN0;
        cpa16(&s.Bh[bPair][bN0],     bh,     true);
        cpa16(&s.Bh[bPair][bN0 + 4], bh + 4, true);
        cpa16(&s.Bl[bPair][bN0],     bl,     true);
        cpa16(&s.Bl[bPair][bN0 + 4], bl + 4, true);
        CPA_COMMIT();
    };

    issue(0, 0);
    int bsel = 0;

    for (int ck = 0; ck < 8; ck++) {
        if (ck < 7) { issue(ck + 1, bsel ^ 1); CPA_WAIT(1); }
        else        { CPA_WAIT(0); }
        __syncthreads();

        GemmSmemT<BM>& s = bufs[bsel];
        #pragma unroll
        for (int kt = 0; kt < 2; kt++) {
            uint afh[2][4], afl[2][4];
            #pragma unroll
            for (int m2 = 0; m2 < 2; m2++) {
                const int r  = wm * 32 + m2 * 16 + g;
                const int wc = 8 * kt + cq;
                afh[m2][0] = s.Ah[r][wc];     afh[m2][1] = s.Ah[r + 8][wc];
                afh[m2][2] = s.Ah[r][wc + 4]; afh[m2][3] = s.Ah[r + 8][wc + 4];
                afl[m2][0] = s.Al[r][wc];     afl[m2][1] = s.Al[r + 8][wc];
                afl[m2][2] = s.Al[r][wc + 4]; afl[m2][3] = s.Al[r + 8][wc + 4];
            }
            #pragma unroll
            for (int nt = 0; nt < NT; nt++) {
                const int n = wn * (NT * 8) + nt * 8 + g;
                uint bfh[2], bfl[2];
                bfh[0] = s.Bh[8 * kt + cq][n];
                bfh[1] = s.Bh[8 * kt + cq + 4][n];
                bfl[0] = s.Bl[8 * kt + cq][n];
                bfl[1] = s.Bl[8 * kt + cq + 4][n];
                #pragma unroll
                for (int m2 = 0; m2 < 2; m2++) {
                    mma_bf16(acc[m2][nt], afh[m2], bfh);
                    mma_bf16(acc[m2][nt], afh[m2], bfl);
                    mma_bf16(acc[m2][nt], afl[m2], bfh);
                }
            }
        }
        __syncthreads();
        bsel ^= 1;
    }

    #pragma unroll
    for (int m2 = 0; m2 < 2; m2++) {
        const int r0 = mt * BM + wm * 32 + m2 * 16 + g;
        const int r1 = r0 + 8;
        #pragma unroll
        for (int nt = 0; nt < NT; nt++) {
            const int cb = wn * (NT * 8) + nt * 8 + 2 * cq;
            const float b0 = bias[cb], b1 = bias[cb + 1];
            if (r0 < LQ) {
                C[(size_t)r0 * ldc + cb]     = (OutT)(acc[m2][nt][0] + b0);
                C[(size_t)r0 * ldc + cb + 1] = (OutT)(acc[m2][nt][1] + b1);
            }
            if (r1 < LQ) {
                C[(size_t)r1 * ldc + cb]     = (OutT)(acc[m2][nt][2] + b0);
                C[(size_t)r1 * ldc + cb + 1] = (OutT)(acc[m2][nt][3] + b1);
            }
        }
    }
}

// ---------------------------------------------------------------------------
// Fused projection GEMM: 512 tiles, BM=128
// ---------------------------------------------------------------------------
__global__ __launch_bounds__(256, 2) void proj_kernel(
    const float* __restrict__ bs,  const float* __restrict__ ba,
    const float* __restrict__ bts, const float* __restrict__ bta,
    const float* __restrict__ bv)
{
    const int t = blockIdx.x;
    if (t < 384) {
        const int mt = t / 6;
        const int nt = t % 6;
        const uint *Bh, *Bl; const float* bias; int ldbw, off;
        switch (nt) {
            case 0:  Bh = g_Wsh;  Bl = g_Wsl;  bias = bs;        ldbw = 256; off = 0;   break;
            case 1:  Bh = g_Wsh;  Bl = g_Wsl;  bias = bs + 128;  ldbw = 256; off = 128; break;
            case 2:  Bh = g_Wah;  Bl = g_Wal;  bias = ba;        ldbw = 128; off = 0;   break;
            case 3:  Bh = g_Wtsh; Bl = g_Wtsl; bias = bts;       ldbw = 256; off = 0;   break;
            case 4:  Bh = g_Wtsh; Bl = g_Wtsl; bias = bts + 128; ldbw = 256; off = 128; break;
            default: Bh = g_Wtah; Bl = g_Wtal; bias = bta;       ldbw = 128; off = 0;   break;
        }
        gemm_mma<128, float>(g_qh, g_ql, Bh + off, Bl + off, ldbw, bias,
                             g_proj + nt * 128, 768, mt);
    } else {
        const int u = t - 384;
        const int mt = u >> 1;
        const int nt = u & 1;
        gemm_mma<128, __half>(g_ih, g_il, g_Wvh + nt * 128, g_Wvl + nt * 128, 256,
                              bv + nt * 128, g_value_h + nt * 128, 256, mt);
    }
}

// Output GEMM: BM=64 -> grid 256 for full-chip fill
__global__ __launch_bounds__(256, 2) void out_kernel(
    const float* __restrict__ bo, float* __restrict__ out)
{
    const int mt = blockIdx.x >> 1;
    const int nt = blockIdx.x & 1;
    gemm_mma<64, float>(g_oh, g_ol, g_Woh + nt * 128, g_Wol + nt * 128, 256,
                        bo + nt * 128, out + nt * 128, 256, mt);
}

// ---------------------------------------------------------------------------
// Sampling kernel: one warp per (q, head).
// Unconditional clamped loads (zero weights outside) for max MLP.
// ---------------------------------------------------------------------------
__global__ __launch_bounds__(256) void sample_kernel(
    const float* __restrict__ ref,
    const float* __restrict__ toff)
{
    __shared__ int   s_row[8][32][4];
    __shared__ float s_w  [8][32][4];

    const int wid   = threadIdx.x >> 5;
    const int lane  = threadIdx.x & 31;
    const int q     = blockIdx.x;
    const int head  = wid;

    const float* prow = g_proj + (size_t)q * 768;

    {
        const int p = lane;
        const int l = p >> 3;
        const int j = p & 7;
        const int W = 48 >> l;
        const int H = 128 >> l;
        const float Wl = (float)W;
        const float Hl = (float)H;

        const float refx = ref[q * 8 + l * 2 + 0];
        const float refy = ref[q * 8 + l * 2 + 1];

        float lg, lx, ly;
        if (j < 4) {
            lg = prow[256 + head * 16 + l * 4 + j];
            const float ox = prow[head * 32 + l * 8 + j * 2 + 0];
            const float oy = prow[head * 32 + l * 8 + j * 2 + 1];
            lx = refx + ox / Wl;
            ly = refy + oy / Hl;
        } else {
            const int kk = j - 4;
            const int tw = kk >> 1;
            lg = prow[640 + head * 16 + l * 4 + kk];
            const float ox = prow[384 + head * 32 + l * 8 + kk * 2 + 0];
            const float oy = prow[384 + head * 32 + l * 8 + kk * 2 + 1];
            const float tx = toff[q * 16 + l * 4 + tw * 2 + 0];
            const float ty = toff[q * 16 + l * 4 + tw * 2 + 1];
            lx = refx + tx + ox / Wl;
            ly = refy + ty + oy / Hl;
        }

        float m = lg;
        #pragma unroll
        for (int o = 16; o > 0; o >>= 1)
            m = fmaxf(m, __shfl_xor_sync(0xffffffffu, m, o));
        float e = expf(lg - m);
        float s = e;
        #pragma unroll
        for (int o = 16; o > 0; o >>= 1)
            s += __shfl_xor_sync(0xffffffffu, s, o);
        const float wgt = e / s;

        const float gx = lx * Wl - 0.5f;
        const float gy = ly * Hl - 0.5f;
        const float fx0 = floorf(gx), fy0 = floorf(gy);
        const int ix0 = (int)fx0, iy0 = (int)fy0;
        const int ix1 = ix0 + 1,  iy1 = iy0 + 1;
        const float wx = gx - fx0, wy = gy - fy0;

        const bool vx0 = (ix0 >= 0) & (ix0 < W);
        const bool vx1 = (ix1 >= 0) & (ix1 < W);
        const bool vy0 = (iy0 >= 0) & (iy0 < H);
        const bool vy1 = (iy1 >= 0) & (iy1 < H);

        // clamped indices (always in range); invalid taps get zero weight
        const int cx0 = min(max(ix0, 0), W - 1);
        const int cx1 = min(max(ix1, 0), W - 1);
        const int cy0 = min(max(iy0, 0), H - 1);
        const int cy1 = min(max(iy1, 0), H - 1);

        const int st = c_lstart[l];
        s_row[wid][p][0] = st + cy0 * W + cx0;
        s_row[wid][p][1] = st + cy0 * W + cx1;
        s_row[wid][p][2] = st + cy1 * W + cx0;
        s_row[wid][p][3] = st + cy1 * W + cx1;
        s_w[wid][p][0] = (vx0 & vy0) ? wgt * (1.f - wx) * (1.f - wy) : 0.f;
        s_w[wid][p][1] = (vx1 & vy0) ? wgt * wx * (1.f - wy)         : 0.f;
        s_w[wid][p][2] = (vx0 & vy1) ? wgt * (1.f - wx) * wy         : 0.f;
        s_w[wid][p][3] = (vx1 & vy1) ? wgt * wx * wy                 : 0.f;
    }
    __syncwarp();

    const int pp = lane >> 4;
    const int d2 = lane & 15;
    const __half2* base = (const __half2*)(g_value_h + head * 32 + 2 * d2);

    float ax = 0.f, ay = 0.f;
    #pragma unroll 4
    for (int pb = 0; pb < 16; pb++) {
        const int p = 2 * pb + pp;
        const int4   rr = *(const int4*)  s_row[wid][p];   // broadcast per half-warp
        const float4 ww = *(const float4*)s_w[wid][p];

        const __half2 v0 = base[(size_t)rr.x * 128];
        const __half2 v1 = base[(size_t)rr.y * 128];
        const __half2 v2 = base[(size_t)rr.z * 128];
        const __half2 v3 = base[(size_t)rr.w * 128];

        float2 f0 = __half22float2(v0);
        float2 f1 = __half22float2(v1);
        float2 f2 = __half22float2(v2);
        float2 f3 = __half22float2(v3);

        ax = fmaf(ww.x, f0.x, ax);  ay = fmaf(ww.x, f0.y, ay);
        ax = fmaf(ww.y, f1.x, ax);  ay = fmaf(ww.y, f1.y, ay);
        ax = fmaf(ww.z, f2.x, ax);  ay = fmaf(ww.z, f2.y, ay);
        ax = fmaf(ww.w, f3.x, ax);  ay = fmaf(ww.w, f3.y, ay);
    }

    ax += __shfl_xor_sync(0xffffffffu, ax, 16);
    ay += __shfl_xor_sync(0xffffffffu, ay, 16);

    if (lane < 16) {
        uint hi, lo;
        split2(ax, ay, hi, lo);
        const int idx = q * 128 + head * 16 + d2;
        g_oh[idx] = hi;
        g_ol[idx] = lo;
    }
}

// ---------------------------------------------------------------------------
// Launch
// ---------------------------------------------------------------------------
extern "C" void kernel_launch(void* const* d_in, const int* in_sizes, int n_in,
                              void* d_out, int out_size)
{
    const float* query = (const float*)d_in[0];
    const float* ref   = (const float*)d_in[1];
    const float* toff  = (const float*)d_in[2];
    const float* inp   = (const float*)d_in[3];
    const float* Wv  = (const float*)d_in[6];
    const float* bv  = (const float*)d_in[7];
    const float* Ws  = (const float*)d_in[8];
    const float* bs  = (const float*)d_in[9];
    const float* Wa  = (const float*)d_in[10];
    const float* ba  = (const float*)d_in[11];
    const float* Wts = (const float*)d_in[12];
    const float* bts = (const float*)d_in[13];
    const float* Wta = (const float*)d_in[14];
    const float* bta = (const float*)d_in[15];
    const float* Wo  = (const float*)d_in[16];
    const float* bo  = (const float*)d_in[17];

    const int smem128 = 2 * (int)sizeof(GemmSmemT<128>);
    const int smem64  = 2 * (int)sizeof(GemmSmemT<64>);
    cudaFuncSetAttribute(proj_kernel, cudaFuncAttributeMaxDynamicSharedMemorySize, smem128);
    cudaFuncSetAttribute(out_kernel,  cudaFuncAttributeMaxDynamicSharedMemorySize, smem64);

    prep_kernel<<<8800, 256>>>(query, inp, Ws, Wa, Wts, Wta, Wv, Wo);

    proj_kernel<<<512, 256, smem128>>>(bs, ba, bts, bta, bv);

    sample_kernel<<<LQ, 256>>>(ref, toff);

    out_kernel<<<256, 256, smem64>>>(bo, (float*)d_out);
}

// round 8
// speedup vs baseline: 3.1515x; 1.1401x over previous
#include <cuda_runtime.h>
#include <cuda_fp16.h>
#include <cuda_bf16.h>
#include <math.h>

// ---------------------------------------------------------------------------
// Problem constants
// ---------------------------------------------------------------------------
#define LQ      8160
#define DMODEL  256

__constant__ int c_lstart[4] = {0, 6144, 7680, 8064};

typedef unsigned int uint;

// ---------------------------------------------------------------------------
// Scratch (device globals; no allocation allowed)
// ---------------------------------------------------------------------------
__device__ uint g_qh [LQ * 128], g_ql [LQ * 128];     // query bf16 hi/lo
__device__ uint g_if16[LQ * 128];                     // input_flatten fp16 pairs
__device__ uint g_of16[LQ * 128];                     // sampled out fp16 pairs
__device__ uint g_Wsh [128 * 256], g_Wsl [128 * 256];
__device__ uint g_Wtsh[128 * 256], g_Wtsl[128 * 256];
__device__ uint g_Wah [128 * 128], g_Wal [128 * 128];
__device__ uint g_Wtah[128 * 128], g_Wtal[128 * 128];
__device__ uint g_Wvf [128 * 256];                    // Wv fp16 pairs
__device__ uint g_Wof [128 * 256];                    // Wo fp16 pairs

__device__ float  g_proj   [LQ * 768];
__device__ __half g_value_h[LQ * DMODEL];

// ---------------------------------------------------------------------------
// helpers
// ---------------------------------------------------------------------------
__device__ __forceinline__ uint pack2bf(float x, float y)
{
    __nv_bfloat162 t = __floats2bfloat162_rn(x, y);
    return *reinterpret_cast<uint*>(&t);
}

__device__ __forceinline__ uint pack2h(float x, float y)
{
    __half2 t = __floats2half2_rn(x, y);
    return *reinterpret_cast<uint*>(&t);
}

__device__ __forceinline__ void split2(float f0, float f1, uint& hi, uint& lo)
{
    float h0 = __bfloat162float(__float2bfloat16_rn(f0));
    float h1 = __bfloat162float(__float2bfloat16_rn(f1));
    hi = pack2bf(h0, h1);
    lo = pack2bf(f0 - h0, f1 - h1);
}

__device__ __forceinline__ void mma_bf16(float* d, const uint* a, const uint* b)
{
    asm volatile(
        "mma.sync.aligned.m16n8k16.row.col.f32.bf16.bf16.f32 "
        "{%0,%1,%2,%3}, {%4,%5,%6,%7}, {%8,%9}, {%0,%1,%2,%3};"
        : "+f"(d[0]), "+f"(d[1]), "+f"(d[2]), "+f"(d[3])
        : "r"(a[0]), "r"(a[1]), "r"(a[2]), "r"(a[3]),
          "r"(b[0]), "r"(b[1]));
}

__device__ __forceinline__ void mma_fp16(float* d, const uint* a, const uint* b)
{
    asm volatile(
        "mma.sync.aligned.m16n8k16.row.col.f32.f16.f16.f32 "
        "{%0,%1,%2,%3}, {%4,%5,%6,%7}, {%8,%9}, {%0,%1,%2,%3};"
        : "+f"(d[0]), "+f"(d[1]), "+f"(d[2]), "+f"(d[3])
        : "r"(a[0]), "r"(a[1]), "r"(a[2]), "r"(a[3]),
          "r"(b[0]), "r"(b[1]));
}

__device__ __forceinline__ void cpa16(void* dst_smem, const void* src, bool valid)
{
    uint ds = (uint)__cvta_generic_to_shared(dst_smem);
    int sz = valid ? 16 : 0;
    asm volatile("cp.async.cg.shared.global [%0], [%1], 16, %2;"
                 :: "r"(ds), "l"(src), "r"(sz));
}
#define CPA_COMMIT()  asm volatile("cp.async.commit_group;")
#define CPA_WAIT(n)   asm volatile("cp.async.wait_group %0;" :: "n"(n))

// ---------------------------------------------------------------------------
// Prep kernel: pack inputs/weights.
//   query -> bf16 hi/lo;  input -> fp16;  Ws/Wa/Wts/Wta -> bf16 hi/lo;
//   Wv/Wo -> fp16.
// ---------------------------------------------------------------------------
__global__ __launch_bounds__(256) void prep_kernel(
    const float* __restrict__ query, const float* __restrict__ inp,
    const float* __restrict__ Ws,  const float* __restrict__ Wa,
    const float* __restrict__ Wts, const float* __restrict__ Wta,
    const float* __restrict__ Wv,  const float* __restrict__ Wo)
{
    const int b = blockIdx.x;
    const int tid = threadIdx.x;

    if (b < 4080) {                 // query hi/lo
        const int idx = b * 256 + tid;
        const int r   = idx >> 7;
        const int kp  = idx & 127;
        const float* src = query + (size_t)r * 256 + 2 * kp;
        uint hi, lo;
        split2(src[0], src[1], hi, lo);
        g_qh[idx] = hi; g_ql[idx] = lo;
    } else if (b < 8160) {          // input fp16
        const int idx = (b - 4080) * 256 + tid;
        const int r   = idx >> 7;
        const int kp  = idx & 127;
        const float* src = inp + (size_t)r * 256 + 2 * kp;
        g_if16[idx] = pack2h(src[0], src[1]);
    } else {
        const int u = b - 8160;
        if (u < 384) {              // bf16 hi/lo weights
            const float* src; uint *dh, *dl; int N; int bl;
            if      (u < 128) { src = Ws;  dh = g_Wsh;  dl = g_Wsl;  N = 256; bl = u; }
            else if (u < 256) { src = Wts; dh = g_Wtsh; dl = g_Wtsl; N = 256; bl = u - 128; }
            else if (u < 320) { src = Wa;  dh = g_Wah;  dl = g_Wal;  N = 128; bl = u - 256; }
            else              { src = Wta; dh = g_Wtah; dl = g_Wtal; N = 128; bl = u - 320; }
            const int idx = bl * 256 + tid;
            const int kp  = idx / N;
            const int n   = idx - kp * N;
            uint hi, lo;
            split2(src[(size_t)(2 * kp) * N + n], src[(size_t)(2 * kp + 1) * N + n], hi, lo);
            dh[idx] = hi; dl[idx] = lo;
        } else {                    // fp16 weights (N=256)
            const float* src; uint* df; int bl;
            if (u < 512) { src = Wv; df = g_Wvf; bl = u - 384; }
            else         { src = Wo; df = g_Wof; bl = u - 512; }
            const int idx = bl * 256 + tid;
            const int kp  = idx >> 8;
            const int n   = idx & 255;
            df[idx] = pack2h(src[(size_t)(2 * kp) * 256 + n],
                             src[(size_t)(2 * kp + 1) * 256 + n]);
        }
    }
}

// ---------------------------------------------------------------------------
// bf16 3-pass GEMM tile (BM=128), cp.async double-buffered
// ---------------------------------------------------------------------------
struct GemmSmemB {
    uint Ah[128][20];
    uint Al[128][20];
    uint Bh[16][136];
    uint Bl[16][136];
};

__device__ __forceinline__ void gemm_mma3(
    const uint* __restrict__ Ahg, const uint* __restrict__ Alg,
    const uint* __restrict__ Bhg, const uint* __restrict__ Blg, int ldbw,
    const float* __restrict__ bias,
    float* __restrict__ C, int ldc,
    int mt)
{
    extern __shared__ char smem_raw[];
    GemmSmemB* bufs = reinterpret_cast<GemmSmemB*>(smem_raw);

    const int tid  = threadIdx.x;
    const int wid  = tid >> 5;
    const int lane = tid & 31;
    const int g    = lane >> 2;
    const int cq   = lane & 3;
    const int wm   = wid >> 1;
    const int wn   = wid & 1;

    const int bPair = tid >> 4;
    const int bN0   = (tid & 15) * 8;

    float acc[2][8][4];
    #pragma unroll
    for (int i = 0; i < 2; i++)
        #pragma unroll
        for (int j = 0; j < 8; j++)
            #pragma unroll
            for (int v = 0; v < 4; v++) acc[i][j][v] = 0.f;

    auto issue = [&](int ck, int bsel) {
        GemmSmemB& s = bufs[bsel];
        #pragma unroll
        for (int i = 0; i < 2; i++) {
            const int op  = i * 256 + tid;
            const int row = op >> 2;
            const int wq  = (op & 3) * 4;
            const int gr  = mt * 128 + row;
            const bool v  = gr < LQ;
            const size_t base = (size_t)(v ? gr : 0) * 128 + ck * 16 + wq;
            cpa16(&s.Ah[row][wq], Ahg + base, v);
            cpa16(&s.Al[row][wq], Alg + base, v);
        }
        const uint* bh = Bhg + (size_t)(ck * 16 + bPair) * ldbw + bN0;
        const uint* bl = Blg + (size_t)(ck * 16 + bPair) * ldbw + bN0;
        cpa16(&s.Bh[bPair][bN0],     bh,     true);
        cpa16(&s.Bh[bPair][bN0 + 4], bh + 4, true);
        cpa16(&s.Bl[bPair][bN0],     bl,     true);
        cpa16(&s.Bl[bPair][bN0 + 4], bl + 4, true);
        CPA_COMMIT();
    };

    issue(0, 0);
    int bsel = 0;

    for (int ck = 0; ck < 8; ck++) {
        if (ck < 7) { issue(ck + 1, bsel ^ 1); CPA_WAIT(1); }
        else        { CPA_WAIT(0); }
        __syncthreads();

        GemmSmemB& s = bufs[bsel];
        #pragma unroll
        for (int kt = 0; kt < 2; kt++) {
            uint afh[2][4], afl[2][4];
            #pragma unroll
            for (int m2 = 0; m2 < 2; m2++) {
                const int r  = wm * 32 + m2 * 16 + g;
                const int wc = 8 * kt + cq;
                afh[m2][0] = s.Ah[r][wc];     afh[m2][1] = s.Ah[r + 8][wc];
                afh[m2][2] = s.Ah[r][wc + 4]; afh[m2][3] = s.Ah[r + 8][wc + 4];
                afl[m2][0] = s.Al[r][wc];     afl[m2][1] = s.Al[r + 8][wc];
                afl[m2][2] = s.Al[r][wc + 4]; afl[m2][3] = s.Al[r + 8][wc + 4];
            }
            #pragma unroll
            for (int nt = 0; nt < 8; nt++) {
                const int n = wn * 64 + nt * 8 + g;
                uint bfh[2], bfl[2];
                bfh[0] = s.Bh[8 * kt + cq][n];
                bfh[1] = s.Bh[8 * kt + cq + 4][n];
                bfl[0] = s.Bl[8 * kt + cq][n];
                bfl[1] = s.Bl[8 * kt + cq + 4][n];
                #pragma unroll
                for (int m2 = 0; m2 < 2; m2++) {
                    mma_bf16(acc[m2][nt], afh[m2], bfh);
                    mma_bf16(acc[m2][nt], afh[m2], bfl);
                    mma_bf16(acc[m2][nt], afl[m2], bfh);
                }
            }
        }
        __syncthreads();
        bsel ^= 1;
    }

    #pragma unroll
    for (int m2 = 0; m2 < 2; m2++) {
        const int r0 = mt * 128 + wm * 32 + m2 * 16 + g;
        const int r1 = r0 + 8;
        #pragma unroll
        for (int nt = 0; nt < 8; nt++) {
            const int cb = wn * 64 + nt * 8 + 2 * cq;
            const float b0 = bias[cb], b1 = bias[cb + 1];
            if (r0 < LQ) {
                C[(size_t)r0 * ldc + cb]     = acc[m2][nt][0] + b0;
                C[(size_t)r0 * ldc + cb + 1] = acc[m2][nt][1] + b1;
            }
            if (r1 < LQ) {
                C[(size_t)r1 * ldc + cb]     = acc[m2][nt][2] + b0;
                C[(size_t)r1 * ldc + cb + 1] = acc[m2][nt][3] + b1;
            }
        }
    }
}

// ---------------------------------------------------------------------------
// fp16 single-pass GEMM tile, templated on BM (64/128)
// ---------------------------------------------------------------------------
template<int BM>
struct GemmSmemH {
    uint A[BM][20];
    uint B[16][136];
};

template<int BM, typename OutT>
__device__ __forceinline__ void gemm_mma1(
    const uint* __restrict__ Ag,
    const uint* __restrict__ Bg, int ldbw,
    const float* __restrict__ bias,
    OutT* __restrict__ C, int ldc,
    int mt)
{
    constexpr int NT = (BM == 128) ? 8 : 4;
    constexpr int ALOOP = BM / 64;
    extern __shared__ char smem_raw[];
    GemmSmemH<BM>* bufs = reinterpret_cast<GemmSmemH<BM>*>(smem_raw);

    const int tid  = threadIdx.x;
    const int wid  = tid >> 5;
    const int lane = tid & 31;
    const int g    = lane >> 2;
    const int cq   = lane & 3;
    const int wm   = (BM == 128) ? (wid >> 1) : (wid >> 2);
    const int wn   = (BM == 128) ? (wid & 1)  : (wid & 3);

    const int bPair = tid >> 4;
    const int bN0   = (tid & 15) * 8;

    float acc[2][NT][4];
    #pragma unroll
    for (int i = 0; i < 2; i++)
        #pragma unroll
        for (int j = 0; j < NT; j++)
            #pragma unroll
            for (int v = 0; v < 4; v++) acc[i][j][v] = 0.f;

    auto issue = [&](int ck, int bsel) {
        GemmSmemH<BM>& s = bufs[bsel];
        #pragma unroll
        for (int i = 0; i < ALOOP; i++) {
            const int op  = i * 256 + tid;
            const int row = op >> 2;
            const int wq  = (op & 3) * 4;
            const int gr  = mt * BM + row;
            const bool v  = gr < LQ;
            const size_t base = (size_t)(v ? gr : 0) * 128 + ck * 16 + wq;
            cpa16(&s.A[row][wq], Ag + base, v);
        }
        const uint* bp = Bg + (size_t)(ck * 16 + bPair) * ldbw + bN0;
        cpa16(&s.B[bPair][bN0],     bp,     true);
        cpa16(&s.B[bPair][bN0 + 4], bp + 4, true);
        CPA_COMMIT();
    };

    issue(0, 0);
    int bsel = 0;

    for (int ck = 0; ck < 8; ck++) {
        if (ck < 7) { issue(ck + 1, bsel ^ 1); CPA_WAIT(1); }
        else        { CPA_WAIT(0); }
        __syncthreads();

        GemmSmemH<BM>& s = bufs[bsel];
        #pragma unroll
        for (int kt = 0; kt < 2; kt++) {
            uint af[2][4];
            #pragma unroll
            for (int m2 = 0; m2 < 2; m2++) {
                const int r  = wm * 32 + m2 * 16 + g;
                const int wc = 8 * kt + cq;
                af[m2][0] = s.A[r][wc];     af[m2][1] = s.A[r + 8][wc];
                af[m2][2] = s.A[r][wc + 4]; af[m2][3] = s.A[r + 8][wc + 4];
            }
            #pragma unroll
            for (int nt = 0; nt < NT; nt++) {
                const int n = wn * (NT * 8) + nt * 8 + g;
                uint bf[2];
                bf[0] = s.B[8 * kt + cq][n];
                bf[1] = s.B[8 * kt + cq + 4][n];
                #pragma unroll
                for (int m2 = 0; m2 < 2; m2++)
                    mma_fp16(acc[m2][nt], af[m2], bf);
            }
        }
        __syncthreads();
        bsel ^= 1;
    }

    #pragma unroll
    for (int m2 = 0; m2 < 2; m2++) {
        const int r0 = mt * BM + wm * 32 + m2 * 16 + g;
        const int r1 = r0 + 8;
        #pragma unroll
        for (int nt = 0; nt < NT; nt++) {
            const int cb = wn * (NT * 8) + nt * 8 + 2 * cq;
            const float b0 = bias[cb], b1 = bias[cb + 1];
            if (r0 < LQ) {
                C[(size_t)r0 * ldc + cb]     = (OutT)(acc[m2][nt][0] + b0);
                C[(size_t)r0 * ldc + cb + 1] = (OutT)(acc[m2][nt][1] + b1);
            }
            if (r1 < LQ) {
                C[(size_t)r1 * ldc + cb]     = (OutT)(acc[m2][nt][2] + b0);
                C[(size_t)r1 * ldc + cb + 1] = (OutT)(acc[m2][nt][3] + b1);
            }
        }
    }
}

// ---------------------------------------------------------------------------
// Fused projection GEMM: 512 tiles
// ---------------------------------------------------------------------------
__global__ __launch_bounds__(256, 2) void proj_kernel(
    const float* __restrict__ bs,  const float* __restrict__ ba,
    const float* __restrict__ bts, const float* __restrict__ bta,
    const float* __restrict__ bv)
{
    const int t = blockIdx.x;
    if (t < 384) {
        const int mt = t / 6;
        const int nt = t % 6;
        const uint *Bh, *Bl; const float* bias; int ldbw, off;
        switch (nt) {
            case 0:  Bh = g_Wsh;  Bl = g_Wsl;  bias = bs;        ldbw = 256; off = 0;   break;
            case 1:  Bh = g_Wsh;  Bl = g_Wsl;  bias = bs + 128;  ldbw = 256; off = 128; break;
            case 2:  Bh = g_Wah;  Bl = g_Wal;  bias = ba;        ldbw = 128; off = 0;   break;
            case 3:  Bh = g_Wtsh; Bl = g_Wtsl; bias = bts;       ldbw = 256; off = 0;   break;
            case 4:  Bh = g_Wtsh; Bl = g_Wtsl; bias = bts + 128; ldbw = 256; off = 128; break;
            default: Bh = g_Wtah; Bl = g_Wtal; bias = bta;       ldbw = 128; off = 0;   break;
        }
        gemm_mma3(g_qh, g_ql, Bh + off, Bl + off, ldbw, bias,
                  g_proj + nt * 128, 768, mt);
    } else {
        const int u = t - 384;
        const int mt = u >> 1;
        const int nt = u & 1;
        gemm_mma1<128, __half>(g_if16, g_Wvf + nt * 128, 256,
                               bv + nt * 128, g_value_h + nt * 128, 256, mt);
    }
}

// Output GEMM: single-pass fp16, BM=64 -> grid 256
__global__ __launch_bounds__(256, 2) void out_kernel(
    const float* __restrict__ bo, float* __restrict__ out)
{
    const int mt = blockIdx.x >> 1;
    const int nt = blockIdx.x & 1;
    gemm_mma1<64, float>(g_of16, g_Wof + nt * 128, 256,
                         bo + nt * 128, out + nt * 128, 256, mt);
}

// ---------------------------------------------------------------------------
// Sampling kernel: one warp per (q, head).
// ---------------------------------------------------------------------------
__global__ __launch_bounds__(256) void sample_kernel(
    const float* __restrict__ ref,
    const float* __restrict__ toff)
{
    __shared__ int   s_row[8][32][4];
    __shared__ float s_w  [8][32][4];

    const int wid   = threadIdx.x >> 5;
    const int lane  = threadIdx.x & 31;
    const int q     = blockIdx.x;
    const int head  = wid;

    const float* prow = g_proj + (size_t)q * 768;

    {
        const int p = lane;
        const int l = p >> 3;
        const int j = p & 7;
        const int W = 48 >> l;
        const int H = 128 >> l;
        const float Wl = (float)W;
        const float Hl = (float)H;

        const float refx = ref[q * 8 + l * 2 + 0];
        const float refy = ref[q * 8 + l * 2 + 1];

        float lg, lx, ly;
        if (j < 4) {
            lg = prow[256 + head * 16 + l * 4 + j];
            const float ox = prow[head * 32 + l * 8 + j * 2 + 0];
            const float oy = prow[head * 32 + l * 8 + j * 2 + 1];
            lx = refx + ox / Wl;
            ly = refy + oy / Hl;
        } else {
            const int kk = j - 4;
            const int tw = kk >> 1;
            lg = prow[640 + head * 16 + l * 4 + kk];
            const float ox = prow[384 + head * 32 + l * 8 + kk * 2 + 0];
            const float oy = prow[384 + head * 32 + l * 8 + kk * 2 + 1];
            const float tx = toff[q * 16 + l * 4 + tw * 2 + 0];
            const float ty = toff[q * 16 + l * 4 + tw * 2 + 1];
            lx = refx + tx + ox / Wl;
            ly = refy + ty + oy / Hl;
        }

        float m = lg;
        #pragma unroll
        for (int o = 16; o > 0; o >>= 1)
            m = fmaxf(m, __shfl_xor_sync(0xffffffffu, m, o));
        float e = expf(lg - m);
        float s = e;
        #pragma unroll
        for (int o = 16; o > 0; o >>= 1)
            s += __shfl_xor_sync(0xffffffffu, s, o);
        const float wgt = e / s;

        const float gx = lx * Wl - 0.5f;
        const float gy = ly * Hl - 0.5f;
        const float fx0 = floorf(gx), fy0 = floorf(gy);
        const int ix0 = (int)fx0, iy0 = (int)fy0;
        const int ix1 = ix0 + 1,  iy1 = iy0 + 1;
        const float wx = gx - fx0, wy = gy - fy0;

        const bool vx0 = (ix0 >= 0) & (ix0 < W);
        const bool vx1 = (ix1 >= 0) & (ix1 < W);
        const bool vy0 = (iy0 >= 0) & (iy0 < H);
        const bool vy1 = (iy1 >= 0) & (iy1 < H);

        const int cx0 = min(max(ix0, 0), W - 1);
        const int cx1 = min(max(ix1, 0), W - 1);
        const int cy0 = min(max(iy0, 0), H - 1);
        const int cy1 = min(max(iy1, 0), H - 1);

        const int st = c_lstart[l];
        s_row[wid][p][0] = st + cy0 * W + cx0;
        s_row[wid][p][1] = st + cy0 * W + cx1;
        s_row[wid][p][2] = st + cy1 * W + cx0;
        s_row[wid][p][3] = st + cy1 * W + cx1;
        s_w[wid][p][0] = (vx0 & vy0) ? wgt * (1.f - wx) * (1.f - wy) : 0.f;
        s_w[wid][p][1] = (vx1 & vy0) ? wgt * wx * (1.f - wy)         : 0.f;
        s_w[wid][p][2] = (vx0 & vy1) ? wgt * (1.f - wx) * wy         : 0.f;
        s_w[wid][p][3] = (vx1 & vy1) ? wgt * wx * wy                 : 0.f;
    }
    __syncwarp();

    const int pp = lane >> 4;
    const int d2 = lane & 15;
    const __half2* base = (const __half2*)(g_value_h + head * 32 + 2 * d2);

    float ax = 0.f, ay = 0.f;
    #pragma unroll 4
    for (int pb = 0; pb < 16; pb++) {
        const int p = 2 * pb + pp;
        const int4   rr = *(const int4*)  s_row[wid][p];
        const float4 ww = *(const float4*)s_w[wid][p];

        const __half2 v0 = base[(size_t)rr.x * 128];
        const __half2 v1 = base[(size_t)rr.y * 128];
        const __half2 v2 = base[(size_t)rr.z * 128];
        const __half2 v3 = base[(size_t)rr.w * 128];

        float2 f0 = __half22float2(v0);
        float2 f1 = __half22float2(v1);
        float2 f2 = __half22float2(v2);
        float2 f3 = __half22float2(v3);

        ax = fmaf(ww.x, f0.x, ax);  ay = fmaf(ww.x, f0.y, ay);
        ax = fmaf(ww.y, f1.x, ax);  ay = fmaf(ww.y, f1.y, ay);
        ax = fmaf(ww.z, f2.x, ax);  ay = fmaf(ww.z, f2.y, ay);
        ax = fmaf(ww.w, f3.x, ax);  ay = fmaf(ww.w, f3.y, ay);
    }

    ax += __shfl_xor_sync(0xffffffffu, ax, 16);
    ay += __shfl_xor_sync(0xffffffffu, ay, 16);

    if (lane < 16)
        g_of16[q * 128 + head * 16 + d2] = pack2h(ax, ay);
}

// ---------------------------------------------------------------------------
// Launch
// ---------------------------------------------------------------------------
extern "C" void kernel_launch(void* const* d_in, const int* in_sizes, int n_in,
                              void* d_out, int out_size)
{
    const float* query = (const float*)d_in[0];
    const float* ref   = (const float*)d_in[1];
    const float* toff  = (const float*)d_in[2];
    const float* inp   = (const float*)d_in[3];
    const float* Wv  = (const float*)d_in[6];
    const float* bv  = (const float*)d_in[7];
    const float* Ws  = (const float*)d_in[8];
    const float* bs  = (const float*)d_in[9];
    const float* Wa  = (const float*)d_in[10];
    const float* ba  = (const float*)d_in[11];
    const float* Wts = (const float*)d_in[12];
    const float* bts = (const float*)d_in[13];
    const float* Wta = (const float*)d_in[14];
    const float* bta = (const float*)d_in[15];
    const float* Wo  = (const float*)d_in[16];
    const float* bo  = (const float*)d_in[17];

    const int smemP = 2 * (int)sizeof(GemmSmemB);      // proj (bf16 path is larger)
    const int smemO = 2 * (int)sizeof(GemmSmemH<64>);
    cudaFuncSetAttribute(proj_kernel, cudaFuncAttributeMaxDynamicSharedMemorySize, smemP);
    cudaFuncSetAttribute(out_kernel,  cudaFuncAttributeMaxDynamicSharedMemorySize, smemO);

    prep_kernel<<<8800, 256>>>(query, inp, Ws, Wa, Wts, Wta, Wv, Wo);

    proj_kernel<<<512, 256, smemP>>>(bs, ba, bts, bta, bv);

    sample_kernel<<<LQ, 256>>>(ref, toff);

    out_kernel<<<256, 256, smemO>>>(bo, (float*)d_out);
}

// round 11
// speedup vs baseline: 3.6349x; 1.1534x over previous
#include <cuda_runtime.h>
#include <cuda_fp16.h>
#include <cuda_bf16.h>
#include <math.h>

// ---------------------------------------------------------------------------
// Problem constants
// ---------------------------------------------------------------------------
#define LQ      8160
#define DMODEL  256

__constant__ int c_lstart[4] = {0, 6144, 7680, 8064};

typedef unsigned int uint;

// ---------------------------------------------------------------------------
// Scratch (device globals; no allocation allowed)
// All operands packed as fp16 pairs (uint = __half2).
// A-side layout: [row][kp], kp = k/2 (pair along K).
// B-side layout: [kp][n]   (pair across adjacent k rows).
// ---------------------------------------------------------------------------
__device__ uint g_qf16[LQ * 128];     // query
__device__ uint g_if16[LQ * 128];     // input_flatten
__device__ uint g_of16[LQ * 128];     // sampled output (written by sample)
__device__ uint g_Wsf [128 * 256];
__device__ uint g_Wtsf[128 * 256];
__device__ uint g_Wvf [128 * 256];
__device__ uint g_Wof [128 * 256];
__device__ uint g_Waf [128 * 128];
__device__ uint g_Wtaf[128 * 128];

__device__ float  g_proj   [LQ * 768];
__device__ __half g_value_h[LQ * DMODEL];

// ---------------------------------------------------------------------------
// helpers
// ---------------------------------------------------------------------------
__device__ __forceinline__ uint pack2h(float x, float y)
{
    __half2 t = __floats2half2_rn(x, y);
    return *reinterpret_cast<uint*>(&t);
}

__device__ __forceinline__ void mma_fp16(float* d, const uint* a, const uint* b)
{
    asm volatile(
        "mma.sync.aligned.m16n8k16.row.col.f32.f16.f16.f32 "
        "{%0,%1,%2,%3}, {%4,%5,%6,%7}, {%8,%9}, {%0,%1,%2,%3};"
        : "+f"(d[0]), "+f"(d[1]), "+f"(d[2]), "+f"(d[3])
        : "r"(a[0]), "r"(a[1]), "r"(a[2]), "r"(a[3]),
          "r"(b[0]), "r"(b[1]));
}

__device__ __forceinline__ void cpa16(void* dst_smem, const void* src, bool valid)
{
    uint ds = (uint)__cvta_generic_to_shared(dst_smem);
    int sz = valid ? 16 : 0;
    asm volatile("cp.async.cg.shared.global [%0], [%1], 16, %2;"
                 :: "r"(ds), "l"(src), "r"(sz));
}
#define CPA_COMMIT()  asm volatile("cp.async.commit_group;")
#define CPA_WAIT(n)   asm volatile("cp.async.wait_group %0;" :: "n"(n))

// ---------------------------------------------------------------------------
// Prep kernel: fp32 -> packed fp16 for all GEMM operands.
// ---------------------------------------------------------------------------
__global__ __launch_bounds__(256) void prep_kernel(
    const float* __restrict__ query, const float* __restrict__ inp,
    const float* __restrict__ Ws,  const float* __restrict__ Wa,
    const float* __restrict__ Wts, const float* __restrict__ Wta,
    const float* __restrict__ Wv,  const float* __restrict__ Wo)
{
    const int b = blockIdx.x;
    const int tid = threadIdx.x;

    if (b < 8160) {                     // A-side: query / input
        const bool isQ = (b < 4080);
        const int  idx = (isQ ? b : b - 4080) * 256 + tid;
        const int  r   = idx >> 7;
        const int  kp  = idx & 127;
        const float* src = (isQ ? query : inp) + (size_t)r * 256 + 2 * kp;
        const uint w = pack2h(src[0], src[1]);
        if (isQ) g_qf16[idx] = w; else g_if16[idx] = w;
    } else {                            // B-side weights
        const int u = b - 8160;
        const float* src; uint* df; int N; int bl;
        if      (u < 128) { src = Ws;  df = g_Wsf;  N = 256; bl = u; }
        else if (u < 256) { src = Wts; df = g_Wtsf; N = 256; bl = u - 128; }
        else if (u < 384) { src = Wv;  df = g_Wvf;  N = 256; bl = u - 256; }
        else if (u < 512) { src = Wo;  df = g_Wof;  N = 256; bl = u - 384; }
        else if (u < 576) { src = Wa;  df = g_Waf;  N = 128; bl = u - 512; }
        else              { src = Wta; df = g_Wtaf; N = 128; bl = u - 576; }
        const int idx = bl * 256 + tid;
        const int kp  = idx / N;
        const int n   = idx - kp * N;
        df[idx] = pack2h(src[(size_t)(2 * kp) * N + n],
                         src[(size_t)(2 * kp + 1) * N + n]);
    }
}

// ---------------------------------------------------------------------------
// fp16 single-pass GEMM tile, templated on BM (64/128), cp.async 2-stage.
// ---------------------------------------------------------------------------
template<int BM>
struct GemmSmemH {
    uint A[BM][20];
    uint B[16][136];
};

template<int BM, typename OutT>
__device__ __forceinline__ void gemm_mma1(
    const uint* __restrict__ Ag,
    const uint* __restrict__ Bg, int ldbw,
    const float* __restrict__ bias,
    OutT* __restrict__ C, int ldc,
    int mt)
{
    constexpr int NT = (BM == 128) ? 8 : 4;
    constexpr int ALOOP = BM / 64;
    extern __shared__ char smem_raw[];
    GemmSmemH<BM>* bufs = reinterpret_cast<GemmSmemH<BM>*>(smem_raw);

    const int tid  = threadIdx.x;
    const int wid  = tid >> 5;
    const int lane = tid & 31;
    const int g    = lane >> 2;
    const int cq   = lane & 3;
    const int wm   = (BM == 128) ? (wid >> 1) : (wid >> 2);
    const int wn   = (BM == 128) ? (wid & 1)  : (wid & 3);

    const int bPair = tid >> 4;
    const int bN0   = (tid & 15) * 8;

    float acc[2][NT][4];
    #pragma unroll
    for (int i = 0; i < 2; i++)
        #pragma unroll
        for (int j = 0; j < NT; j++)
            #pragma unroll
            for (int v = 0; v < 4; v++) acc[i][j][v] = 0.f;

    auto issue = [&](int ck, int bsel) {
        GemmSmemH<BM>& s = bufs[bsel];
        #pragma unroll
        for (int i = 0; i < ALOOP; i++) {
            const int op  = i * 256 + tid;
            const int row = op >> 2;
            const int wq  = (op & 3) * 4;
            const int gr  = mt * BM + row;
            const bool v  = gr < LQ;
            const size_t base = (size_t)(v ? gr : 0) * 128 + ck * 16 + wq;
            cpa16(&s.A[row][wq], Ag + base, v);
        }
        const uint* bp = Bg + (size_t)(ck * 16 + bPair) * ldbw + bN0;
        cpa16(&s.B[bPair][bN0],     bp,     true);
        cpa16(&s.B[bPair][bN0 + 4], bp + 4, true);
        CPA_COMMIT();
    };

    issue(0, 0);
    int bsel = 0;

    for (int ck = 0; ck < 8; ck++) {
        if (ck < 7) { issue(ck + 1, bsel ^ 1); CPA_WAIT(1); }
        else        { CPA_WAIT(0); }
        __syncthreads();

        GemmSmemH<BM>& s = bufs[bsel];
        #pragma unroll
        for (int kt = 0; kt < 2; kt++) {
            uint af[2][4];
            #pragma unroll
            for (int m2 = 0; m2 < 2; m2++) {
                const int r  = wm * 32 + m2 * 16 + g;
                const int wc = 8 * kt + cq;
                af[m2][0] = s.A[r][wc];     af[m2][1] = s.A[r + 8][wc];
                af[m2][2] = s.A[r][wc + 4]; af[m2][3] = s.A[r + 8][wc + 4];
            }
            #pragma unroll
            for (int nt = 0; nt < NT; nt++) {
                const int n = wn * (NT * 8) + nt * 8 + g;
                uint bf[2];
                bf[0] = s.B[8 * kt + cq][n];
                bf[1] = s.B[8 * kt + cq + 4][n];
                #pragma unroll
                for (int m2 = 0; m2 < 2; m2++)
                    mma_fp16(acc[m2][nt], af[m2], bf);
            }
        }
        __syncthreads();
        bsel ^= 1;
    }

    #pragma unroll
    for (int m2 = 0; m2 < 2; m2++) {
        const int r0 = mt * BM + wm * 32 + m2 * 16 + g;
        const int r1 = r0 + 8;
        #pragma unroll
        for (int nt = 0; nt < NT; nt++) {
            const int cb = wn * (NT * 8) + nt * 8 + 2 * cq;
            const float b0 = bias[cb], b1 = bias[cb + 1];
            if (r0 < LQ) {
                C[(size_t)r0 * ldc + cb]     = (OutT)(acc[m2][nt][0] + b0);
                C[(size_t)r0 * ldc + cb + 1] = (OutT)(acc[m2][nt][1] + b1);
            }
            if (r1 < LQ) {
                C[(size_t)r1 * ldc + cb]     = (OutT)(acc[m2][nt][2] + b0);
                C[(size_t)r1 * ldc + cb + 1] = (OutT)(acc[m2][nt][3] + b1);
            }
        }
    }
}

// ---------------------------------------------------------------------------
// Fused projection GEMM: 512 tiles, all single-pass fp16
// ---------------------------------------------------------------------------
__global__ __launch_bounds__(256, 2) void proj_kernel(
    const float* __restrict__ bs,  const float* __restrict__ ba,
    const float* __restrict__ bts, const float* __restrict__ bta,
    const float* __restrict__ bv)
{
    const int t = blockIdx.x;
    if (t < 384) {
        const int mt = t / 6;
        const int nt = t % 6;
        const uint* B; const float* bias; int ldbw;
        switch (nt) {
            case 0:  B = g_Wsf;        bias = bs;        ldbw = 256; break;
            case 1:  B = g_Wsf + 128;  bias = bs + 128;  ldbw = 256; break;
            case 2:  B = g_Waf;        bias = ba;        ldbw = 128; break;
            case 3:  B = g_Wtsf;       bias = bts;       ldbw = 256; break;
            case 4:  B = g_Wtsf + 128; bias = bts + 128; ldbw = 256; break;
            default: B = g_Wtaf;       bias = bta;       ldbw = 128; break;
        }
        gemm_mma1<128, float>(g_qf16, B, ldbw, bias, g_proj + nt * 128, 768, mt);
    } else {
        const int u = t - 384;
        const int mt = u >> 1;
        const int nt = u & 1;
        gemm_mma1<128, __half>(g_if16, g_Wvf + nt * 128, 256,
                               bv + nt * 128, g_value_h + nt * 128, 256, mt);
    }
}

// Output GEMM: single-pass fp16, BM=64 -> grid 256
__global__ __launch_bounds__(256, 2) void out_kernel(
    const float* __restrict__ bo, float* __restrict__ out)
{
    const int mt = blockIdx.x >> 1;
    const int nt = blockIdx.x & 1;
    gemm_mma1<64, float>(g_of16, g_Wof + nt * 128, 256,
                         bo + nt * 128, out + nt * 128, 256, mt);
}

// ---------------------------------------------------------------------------
// Sampling kernel: one warp per (q, head).
// Full unroll of the accumulate loop for max load batching (MLP).
// ---------------------------------------------------------------------------
__global__ __launch_bounds__(256) void sample_kernel(
    const float* __restrict__ ref,
    const float* __restrict__ toff)
{
    __shared__ int   s_row[8][32][4];
    __shared__ float s_w  [8][32][4];

    const int wid   = threadIdx.x >> 5;
    const int lane  = threadIdx.x & 31;
    const int q     = blockIdx.x;
    const int head  = wid;

    const float* prow = g_proj + (size_t)q * 768;

    {
        const int p = lane;
        const int l = p >> 3;
        const int j = p & 7;
        const int W = 48 >> l;
        const int H = 128 >> l;
        const float Wl = (float)W;
        const float Hl = (float)H;

        const float refx = ref[q * 8 + l * 2 + 0];
        const float refy = ref[q * 8 + l * 2 + 1];

        float lg, lx, ly;
        if (j < 4) {
            lg = prow[256 + head * 16 + l * 4 + j];
            const float ox = prow[head * 32 + l * 8 + j * 2 + 0];
            const float oy = prow[head * 32 + l * 8 + j * 2 + 1];
            lx = refx + ox / Wl;
            ly = refy + oy / Hl;
        } else {
            const int kk = j - 4;
            const int tw = kk >> 1;
            lg = prow[640 + head * 16 + l * 4 + kk];
            const float ox = prow[384 + head * 32 + l * 8 + kk * 2 + 0];
            const float oy = prow[384 + head * 32 + l * 8 + kk * 2 + 1];
            const float tx = toff[q * 16 + l * 4 + tw * 2 + 0];
            const float ty = toff[q * 16 + l * 4 + tw * 2 + 1];
            lx = refx + tx + ox / Wl;
            ly = refy + ty + oy / Hl;
        }

        float m = lg;
        #pragma unroll
        for (int o = 16; o > 0; o >>= 1)
            m = fmaxf(m, __shfl_xor_sync(0xffffffffu, m, o));
        float e = expf(lg - m);
        float s = e;
        #pragma unroll
        for (int o = 16; o > 0; o >>= 1)
            s += __shfl_xor_sync(0xffffffffu, s, o);
        const float wgt = e / s;

        const float gx = lx * Wl - 0.5f;
        const float gy = ly * Hl - 0.5f;
        const float fx0 = floorf(gx), fy0 = floorf(gy);
        const int ix0 = (int)fx0, iy0 = (int)fy0;
        const int ix1 = ix0 + 1,  iy1 = iy0 + 1;
        const float wx = gx - fx0, wy = gy - fy0;

        const bool vx0 = (ix0 >= 0) & (ix0 < W);
        const bool vx1 = (ix1 >= 0) & (ix1 < W);
        const bool vy0 = (iy0 >= 0) & (iy0 < H);
        const bool vy1 = (iy1 >= 0) & (iy1 < H);

        const int cx0 = min(max(ix0, 0), W - 1);
        const int cx1 = min(max(ix1, 0), W - 1);
        const int cy0 = min(max(iy0, 0), H - 1);
        const int cy1 = min(max(iy1, 0), H - 1);

        const int st = c_lstart[l];
        s_row[wid][p][0] = st + cy0 * W + cx0;
        s_row[wid][p][1] = st + cy0 * W + cx1;
        s_row[wid][p][2] = st + cy1 * W + cx0;
        s_row[wid][p][3] = st + cy1 * W + cx1;
        s_w[wid][p][0] = (vx0 & vy0) ? wgt * (1.f - wx) * (1.f - wy) : 0.f;
        s_w[wid][p][1] = (vx1 & vy0) ? wgt * wx * (1.f - wy)         : 0.f;
        s_w[wid][p][2] = (vx0 & vy1) ? wgt * (1.f - wx) * wy         : 0.f;
        s_w[wid][p][3] = (vx1 & vy1) ? wgt * wx * wy                 : 0.f;
    }
    __syncwarp();

    const int pp = lane >> 4;
    const int d2 = lane & 15;
    const __half2* base = (const __half2*)(g_value_h + head * 32 + 2 * d2);

    float ax = 0.f, ay = 0.f;
    #pragma unroll
    for (int pb = 0; pb < 16; pb++) {
        const int p = 2 * pb + pp;
        const int4   rr = *(const int4*)  s_row[wid][p];
        const float4 ww = *(const float4*)s_w[wid][p];

        const __half2 v0 = base[(size_t)rr.x * 128];
        const __half2 v1 = base[(size_t)rr.y * 128];
        const __half2 v2 = base[(size_t)rr.z * 128];
        const __half2 v3 = base[(size_t)rr.w * 128];

        float2 f0 = __half22float2(v0);
        float2 f1 = __half22float2(v1);
        float2 f2 = __half22float2(v2);
        float2 f3 = __half22float2(v3);

        ax = fmaf(ww.x, f0.x, ax);  ay = fmaf(ww.x, f0.y, ay);
        ax = fmaf(ww.y, f1.x, ax);  ay = fmaf(ww.y, f1.y, ay);
        ax = fmaf(ww.z, f2.x, ax);  ay = fmaf(ww.z, f2.y, ay);
        ax = fmaf(ww.w, f3.x, ax);  ay = fmaf(ww.w, f3.y, ay);
    }

    ax += __shfl_xor_sync(0xffffffffu, ax, 16);
    ay += __shfl_xor_sync(0xffffffffu, ay, 16);

    if (lane < 16)
        g_of16[q * 128 + head * 16 + d2] = pack2h(ax, ay);
}

// ---------------------------------------------------------------------------
// Launch
// ---------------------------------------------------------------------------
extern "C" void kernel_launch(void* const* d_in, const int* in_sizes, int n_in,
                              void* d_out, int out_size)
{
    const float* query = (const float*)d_in[0];
    const float* ref   = (const float*)d_in[1];
    const float* toff  = (const float*)d_in[2];
    const float* inp   = (const float*)d_in[3];
    const float* Wv  = (const float*)d_in[6];
    const float* bv  = (const float*)d_in[7];
    const float* Ws  = (const float*)d_in[8];
    const float* bs  = (const float*)d_in[9];
    const float* Wa  = (const float*)d_in[10];
    const float* ba  = (const float*)d_in[11];
    const float* Wts = (const float*)d_in[12];
    const float* bts = (const float*)d_in[13];
    const float* Wta = (const float*)d_in[14];
    const float* bta = (const float*)d_in[15];
    const float* Wo  = (const float*)d_in[16];
    const float* bo  = (const float*)d_in[17];

    const int smemP = 2 * (int)sizeof(GemmSmemH<128>);
    const int smemO = 2 * (int)sizeof(GemmSmemH<64>);
    cudaFuncSetAttribute(proj_kernel, cudaFuncAttributeMaxDynamicSharedMemorySize, smemP);
    cudaFuncSetAttribute(out_kernel,  cudaFuncAttributeMaxDynamicSharedMemorySize, smemO);

    prep_kernel<<<8800, 256>>>(query, inp, Ws, Wa, Wts, Wta, Wv, Wo);

    proj_kernel<<<512, 256, smemP>>>(bs, ba, bts, bta, bv);

    sample_kernel<<<LQ, 256>>>(ref, toff);

    out_kernel<<<256, 256, smemO>>>(bo, (float*)d_out);
}

// round 13
// speedup vs baseline: 3.9324x; 1.0818x over previous
#include <cuda_runtime.h>
#include <cuda_fp16.h>
#include <cuda_bf16.h>
#include <math.h>

// ---------------------------------------------------------------------------
// Problem constants
// ---------------------------------------------------------------------------
#define LQ      8160
#define DMODEL  256

__constant__ int c_lstart[4] = {0, 6144, 7680, 8064};

typedef unsigned int uint;

// ---------------------------------------------------------------------------
// Scratch (device globals; no allocation allowed)
// All GEMM operands packed as fp16 pairs (uint = __half2).
// A-side layout: [row][kp], kp = k/2. B-side: [kp][n].
// ---------------------------------------------------------------------------
__device__ uint g_qf16[LQ * 128];
__device__ uint g_if16[LQ * 128];
__device__ uint g_of16[LQ * 128];
__device__ uint g_Wsf [128 * 256];
__device__ uint g_Wtsf[128 * 256];
__device__ uint g_Wvf [128 * 256];
__device__ uint g_Wof [128 * 256];
__device__ uint g_Waf [128 * 128];
__device__ uint g_Wtaf[128 * 128];

__device__ float  g_proj   [LQ * 768];
__device__ __half g_value_h[LQ * DMODEL];

// ---------------------------------------------------------------------------
// helpers
// ---------------------------------------------------------------------------
__device__ __forceinline__ uint pack2h(float x, float y)
{
    __half2 t = __floats2half2_rn(x, y);
    return *reinterpret_cast<uint*>(&t);
}

__device__ __forceinline__ void mma_fp16(float* d, const uint* a, const uint* b)
{
    asm volatile(
        "mma.sync.aligned.m16n8k16.row.col.f32.f16.f16.f32 "
        "{%0,%1,%2,%3}, {%4,%5,%6,%7}, {%8,%9}, {%0,%1,%2,%3};"
        : "+f"(d[0]), "+f"(d[1]), "+f"(d[2]), "+f"(d[3])
        : "r"(a[0]), "r"(a[1]), "r"(a[2]), "r"(a[3]),
          "r"(b[0]), "r"(b[1]));
}

__device__ __forceinline__ void cpa16(void* dst_smem, const void* src, bool valid)
{
    uint ds = (uint)__cvta_generic_to_shared(dst_smem);
    int sz = valid ? 16 : 0;
    asm volatile("cp.async.cg.shared.global [%0], [%1], 16, %2;"
                 :: "r"(ds), "l"(src), "r"(sz));
}
#define CPA_COMMIT()  asm volatile("cp.async.commit_group;")
#define CPA_WAIT(n)   asm volatile("cp.async.wait_group %0;" :: "n"(n))

// ---------------------------------------------------------------------------
// Prep kernel: fp32 -> packed fp16, 4 output words (16 B) per thread.
//   blocks [0,1020): query   [1020,2040): input
//   blocks [2040,2200): weights (Ws 32, Wts 32, Wv 32, Wo 32, Wa 16, Wta 16)
// ---------------------------------------------------------------------------
__global__ __launch_bounds__(256) void prep_kernel(
    const float* __restrict__ query, const float* __restrict__ inp,
    const float* __restrict__ Ws,  const float* __restrict__ Wa,
    const float* __restrict__ Wts, const float* __restrict__ Wta,
    const float* __restrict__ Wv,  const float* __restrict__ Wo)
{
    const int b = blockIdx.x;
    const int tid = threadIdx.x;

    if (b < 2040) {                     // A-side
        const bool isQ = (b < 1020);
        const int  wb  = ((isQ ? b : b - 1020) * 256 + tid) * 4;  // word index
        const int  r   = wb >> 7;
        const int  kp  = wb & 127;      // 4-aligned
        const float* src = (isQ ? query : inp) + (size_t)r * 256 + 2 * kp;
        const float4 f0 = *(const float4*)(src);
        const float4 f1 = *(const float4*)(src + 4);
        uint4 o;
        o.x = pack2h(f0.x, f0.y); o.y = pack2h(f0.z, f0.w);
        o.z = pack2h(f1.x, f1.y); o.w = pack2h(f1.z, f1.w);
        *(uint4*)&(isQ ? g_qf16 : g_if16)[wb] = o;
    } else {                            // B-side weights
        const int u = b - 2040;
        const float* src; uint* df; int N; int bl;
        if      (u < 32)  { src = Ws;  df = g_Wsf;  N = 256; bl = u; }
        else if (u < 64)  { src = Wts; df = g_Wtsf; N = 256; bl = u - 32; }
        else if (u < 96)  { src = Wv;  df = g_Wvf;  N = 256; bl = u - 64; }
        else if (u < 128) { src = Wo;  df = g_Wof;  N = 256; bl = u - 96; }
        else if (u < 144) { src = Wa;  df = g_Waf;  N = 128; bl = u - 128; }
        else              { src = Wta; df = g_Wtaf; N = 128; bl = u - 144; }
        const int wb = (bl * 256 + tid) * 4;
        const int kp = wb / N;
        const int n  = wb - kp * N;     // 4-aligned, same kp for all 4 words
        const float4 r0 = *(const float4*)(src + (size_t)(2 * kp)     * N + n);
        const float4 r1 = *(const float4*)(src + (size_t)(2 * kp + 1) * N + n);
        uint4 o;
        o.x = pack2h(r0.x, r1.x); o.y = pack2h(r0.y, r1.y);
        o.z = pack2h(r0.z, r1.z); o.w = pack2h(r0.w, r1.w);
        *(uint4*)&df[wb] = o;
    }
}

// ---------------------------------------------------------------------------
// fp16 single-pass GEMM tile, templated on BM (64/128), cp.async 2-stage.
// ---------------------------------------------------------------------------
template<int BM>
struct GemmSmemH {
    uint A[BM][20];
    uint B[16][136];
};

template<int BM, typename OutT>
__device__ __forceinline__ void gemm_mma1(
    const uint* __restrict__ Ag,
    const uint* __restrict__ Bg, int ldbw,
    const float* __restrict__ bias,
    OutT* __restrict__ C, int ldc,
    int mt)
{
    constexpr int NT = (BM == 128) ? 8 : 4;
    constexpr int ALOOP = BM / 64;
    extern __shared__ char smem_raw[];
    GemmSmemH<BM>* bufs = reinterpret_cast<GemmSmemH<BM>*>(smem_raw);

    const int tid  = threadIdx.x;
    const int wid  = tid >> 5;
    const int lane = tid & 31;
    const int g    = lane >> 2;
    const int cq   = lane & 3;
    const int wm   = (BM == 128) ? (wid >> 1) : (wid >> 2);
    const int wn   = (BM == 128) ? (wid & 1)  : (wid & 3);

    const int bPair = tid >> 4;
    const int bN0   = (tid & 15) * 8;

    float acc[2][NT][4];
    #pragma unroll
    for (int i = 0; i < 2; i++)
        #pragma unroll
        for (int j = 0; j < NT; j++)
            #pragma unroll
            for (int v = 0; v < 4; v++) acc[i][j][v] = 0.f;

    auto issue = [&](int ck, int bsel) {
        GemmSmemH<BM>& s = bufs[bsel];
        #pragma unroll
        for (int i = 0; i < ALOOP; i++) {
            const int op  = i * 256 + tid;
            const int row = op >> 2;
            const int wq  = (op & 3) * 4;
            const int gr  = mt * BM + row;
            const bool v  = gr < LQ;
            const size_t base = (size_t)(v ? gr : 0) * 128 + ck * 16 + wq;
            cpa16(&s.A[row][wq], Ag + base, v);
        }
        const uint* bp = Bg + (size_t)(ck * 16 + bPair) * ldbw + bN0;
        cpa16(&s.B[bPair][bN0],     bp,     true);
        cpa16(&s.B[bPair][bN0 + 4], bp + 4, true);
        CPA_COMMIT();
    };

    issue(0, 0);
    int bsel = 0;

    for (int ck = 0; ck < 8; ck++) {
        if (ck < 7) { issue(ck + 1, bsel ^ 1); CPA_WAIT(1); }
        else        { CPA_WAIT(0); }
        __syncthreads();

        GemmSmemH<BM>& s = bufs[bsel];
        #pragma unroll
        for (int kt = 0; kt < 2; kt++) {
            uint af[2][4];
            #pragma unroll
            for (int m2 = 0; m2 < 2; m2++) {
                const int r  = wm * 32 + m2 * 16 + g;
                const int wc = 8 * kt + cq;
                af[m2][0] = s.A[r][wc];     af[m2][1] = s.A[r + 8][wc];
                af[m2][2] = s.A[r][wc + 4]; af[m2][3] = s.A[r + 8][wc + 4];
            }
            #pragma unroll
            for (int nt = 0; nt < NT; nt++) {
                const int n = wn * (NT * 8) + nt * 8 + g;
                uint bf[2];
                bf[0] = s.B[8 * kt + cq][n];
                bf[1] = s.B[8 * kt + cq + 4][n];
                #pragma unroll
                for (int m2 = 0; m2 < 2; m2++)
                    mma_fp16(acc[m2][nt], af[m2], bf);
            }
        }
        __syncthreads();
        bsel ^= 1;
    }

    #pragma unroll
    for (int m2 = 0; m2 < 2; m2++) {
        const int r0 = mt * BM + wm * 32 + m2 * 16 + g;
        const int r1 = r0 + 8;
        #pragma unroll
        for (int nt = 0; nt < NT; nt++) {
            const int cb = wn * (NT * 8) + nt * 8 + 2 * cq;
            const float b0 = bias[cb], b1 = bias[cb + 1];
            if (r0 < LQ) {
                C[(size_t)r0 * ldc + cb]     = (OutT)(acc[m2][nt][0] + b0);
                C[(size_t)r0 * ldc + cb + 1] = (OutT)(acc[m2][nt][1] + b1);
            }
            if (r1 < LQ) {
                C[(size_t)r1 * ldc + cb]     = (OutT)(acc[m2][nt][2] + b0);
                C[(size_t)r1 * ldc + cb + 1] = (OutT)(acc[m2][nt][3] + b1);
            }
        }
    }
}

// ---------------------------------------------------------------------------
// Fused projection GEMM: 512 tiles, all single-pass fp16
// ---------------------------------------------------------------------------
__global__ __launch_bounds__(256, 2) void proj_kernel(
    const float* __restrict__ bs,  const float* __restrict__ ba,
    const float* __restrict__ bts, const float* __restrict__ bta,
    const float* __restrict__ bv)
{
    const int t = blockIdx.x;
    if (t < 384) {
        const int mt = t / 6;
        const int nt = t % 6;
        const uint* B; const float* bias; int ldbw;
        switch (nt) {
            case 0:  B = g_Wsf;        bias = bs;        ldbw = 256; break;
            case 1:  B = g_Wsf + 128;  bias = bs + 128;  ldbw = 256; break;
            case 2:  B = g_Waf;        bias = ba;        ldbw = 128; break;
            case 3:  B = g_Wtsf;       bias = bts;       ldbw = 256; break;
            case 4:  B = g_Wtsf + 128; bias = bts + 128; ldbw = 256; break;
            default: B = g_Wtaf;       bias = bta;       ldbw = 128; break;
        }
        gemm_mma1<128, float>(g_qf16, B, ldbw, bias, g_proj + nt * 128, 768, mt);
    } else {
        const int u = t - 384;
        const int mt = u >> 1;
        const int nt = u & 1;
        gemm_mma1<128, __half>(g_if16, g_Wvf + nt * 128, 256,
                               bv + nt * 128, g_value_h + nt * 128, 256, mt);
    }
}

// Output GEMM: single-pass fp16, BM=64 -> grid 256
__global__ __launch_bounds__(256, 2) void out_kernel(
    const float* __restrict__ bo, float* __restrict__ out)
{
    const int mt = blockIdx.x >> 1;
    const int nt = blockIdx.x & 1;
    gemm_mma1<64, float>(g_of16, g_Wof + nt * 128, 256,
                         bo + nt * 128, out + nt * 128, 256, mt);
}

// ---------------------------------------------------------------------------
// Sampling kernel: one warp per (q, head).
// Accumulate phase: lane = tap(2b) x c8(3b); one warp-LDG.64 covers a whole
// point (4 taps x 32 channels). Cross-tap reduce via shfl-xor 8,16.
// ---------------------------------------------------------------------------
__global__ __launch_bounds__(256) void sample_kernel(
    const float* __restrict__ ref,
    const float* __restrict__ toff)
{
    __shared__ float2 s_rw[8][32][4];    // x = row (as int bits), y = fused weight

    const int wid   = threadIdx.x >> 5;
    const int lane  = threadIdx.x & 31;
    const int q     = blockIdx.x;
    const int head  = wid;

    const float* prow = g_proj + (size_t)q * 768;

    // ---- setup: lane == point index p ----
    {
        const int p = lane;
        const int l = p >> 3;
        const int j = p & 7;
        const int W = 48 >> l;
        const int H = 128 >> l;
        const float Wl = (float)W;
        const float Hl = (float)H;

        const float refx = ref[q * 8 + l * 2 + 0];
        const float refy = ref[q * 8 + l * 2 + 1];

        float lg, lx, ly;
        if (j < 4) {
            lg = prow[256 + head * 16 + l * 4 + j];
            const float ox = prow[head * 32 + l * 8 + j * 2 + 0];
            const float oy = prow[head * 32 + l * 8 + j * 2 + 1];
            lx = refx + ox / Wl;
            ly = refy + oy / Hl;
        } else {
            const int kk = j - 4;
            const int tw = kk >> 1;
            lg = prow[640 + head * 16 + l * 4 + kk];
            const float ox = prow[384 + head * 32 + l * 8 + kk * 2 + 0];
            const float oy = prow[384 + head * 32 + l * 8 + kk * 2 + 1];
            const float tx = toff[q * 16 + l * 4 + tw * 2 + 0];
            const float ty = toff[q * 16 + l * 4 + tw * 2 + 1];
            lx = refx + tx + ox / Wl;
            ly = refy + ty + oy / Hl;
        }

        float m = lg;
        #pragma unroll
        for (int o = 16; o > 0; o >>= 1)
            m = fmaxf(m, __shfl_xor_sync(0xffffffffu, m, o));
        float e = expf(lg - m);
        float s = e;
        #pragma unroll
        for (int o = 16; o > 0; o >>= 1)
            s += __shfl_xor_sync(0xffffffffu, s, o);
        const float wgt = e / s;

        const float gx = lx * Wl - 0.5f;
        const float gy = ly * Hl - 0.5f;
        const float fx0 = floorf(gx), fy0 = floorf(gy);
        const int ix0 = (int)fx0, iy0 = (int)fy0;
        const int ix1 = ix0 + 1,  iy1 = iy0 + 1;
        const float wx = gx - fx0, wy = gy - fy0;

        const bool vx0 = (ix0 >= 0) & (ix0 < W);
        const bool vx1 = (ix1 >= 0) & (ix1 < W);
        const bool vy0 = (iy0 >= 0) & (iy0 < H);
        const bool vy1 = (iy1 >= 0) & (iy1 < H);

        const int cx0 = min(max(ix0, 0), W - 1);
        const int cx1 = min(max(ix1, 0), W - 1);
        const int cy0 = min(max(iy0, 0), H - 1);
        const int cy1 = min(max(iy1, 0), H - 1);

        const int st = c_lstart[l];
        s_rw[wid][p][0] = make_float2(
            __int_as_float(st + cy0 * W + cx0),
            (vx0 & vy0) ? wgt * (1.f - wx) * (1.f - wy) : 0.f);
        s_rw[wid][p][1] = make_float2(
            __int_as_float(st + cy0 * W + cx1),
            (vx1 & vy0) ? wgt * wx * (1.f - wy) : 0.f);
        s_rw[wid][p][2] = make_float2(
            __int_as_float(st + cy1 * W + cx0),
            (vx0 & vy1) ? wgt * (1.f - wx) * wy : 0.f);
        s_rw[wid][p][3] = make_float2(
            __int_as_float(st + cy1 * W + cx1),
            (vx1 & vy1) ? wgt * wx * wy : 0.f);
    }
    __syncwarp();

    // ---- accumulate: lane = tap*8 + c8; channels [4*c8, 4*c8+4) ----
    const int tap = lane >> 3;
    const int c8  = lane & 7;
    const __half* vbase = g_value_h + head * 32 + 4 * c8;

    float a0 = 0.f, a1 = 0.f, a2 = 0.f, a3 = 0.f;
    #pragma unroll
    for (int p = 0; p < 32; p++) {
        const float2 rw = s_rw[wid][p][tap];
        const int    r  = __float_as_int(rw.x);
        const float  w  = rw.y;
        const uint2  v  = *(const uint2*)(vbase + (size_t)r * 256);
        const float2 f0 = __half22float2(*(const __half2*)&v.x);
        const float2 f1 = __half22float2(*(const __half2*)&v.y);
        a0 = fmaf(w, f0.x, a0);
        a1 = fmaf(w, f0.y, a1);
        a2 = fmaf(w, f1.x, a2);
        a3 = fmaf(w, f1.y, a3);
    }

    // reduce across the 4 tap groups
    a0 += __shfl_xor_sync(0xffffffffu, a0, 8);
    a1 += __shfl_xor_sync(0xffffffffu, a1, 8);
    a2 += __shfl_xor_sync(0xffffffffu, a2, 8);
    a3 += __shfl_xor_sync(0xffffffffu, a3, 8);
    a0 += __shfl_xor_sync(0xffffffffu, a0, 16);
    a1 += __shfl_xor_sync(0xffffffffu, a1, 16);
    a2 += __shfl_xor_sync(0xffffffffu, a2, 16);
    a3 += __shfl_xor_sync(0xffffffffu, a3, 16);

    if (lane < 8) {
        uint2 o;
        o.x = pack2h(a0, a1);
        o.y = pack2h(a2, a3);
        *(uint2*)&g_of16[q * 128 + head * 16 + 2 * c8] = o;
    }
}

// ---------------------------------------------------------------------------
// Launch
// ---------------------------------------------------------------------------
extern "C" void kernel_launch(void* const* d_in, const int* in_sizes, int n_in,
                              void* d_out, int out_size)
{
    const float* query = (const float*)d_in[0];
    const float* ref   = (const float*)d_in[1];
    const float* toff  = (const float*)d_in[2];
    const float* inp   = (const float*)d_in[3];
    const float* Wv  = (const float*)d_in[6];
    const float* bv  = (const float*)d_in[7];
    const float* Ws  = (const float*)d_in[8];
    const float* bs  = (const float*)d_in[9];
    const float* Wa  = (const float*)d_in[10];
    const float* ba  = (const float*)d_in[11];
    const float* Wts = (const float*)d_in[12];
    const float* bts = (const float*)d_in[13];
    const float* Wta = (const float*)d_in[14];
    const float* bta = (const float*)d_in[15];
    const float* Wo  = (const float*)d_in[16];
    const float* bo  = (const float*)d_in[17];

    const int smemP = 2 * (int)sizeof(GemmSmemH<128>);
    const int smemO = 2 * (int)sizeof(GemmSmemH<64>);
    cudaFuncSetAttribute(proj_kernel, cudaFuncAttributeMaxDynamicSharedMemorySize, smemP);
    cudaFuncSetAttribute(out_kernel,  cudaFuncAttributeMaxDynamicSharedMemorySize, smemO);

    prep_kernel<<<2200, 256>>>(query, inp, Ws, Wa, Wts, Wta, Wv, Wo);

    proj_kernel<<<512, 256, smemP>>>(bs, ba, bts, bta, bv);

    sample_kernel<<<LQ, 256>>>(ref, toff);

    out_kernel<<<256, 256, smemO>>>(bo, (float*)d_out);
}